// round 4
// baseline (speedup 1.0000x reference)
#include <cuda_runtime.h>
#include <cuda_bf16.h>
#include <math.h>

// Problem constants
#define B_  2
#define S_  2048
#define DM_ 2048
#define NH_ 16
#define HD_ 128
#define BS_ (B_ * S_)
#define SCALE_ 0.08838834764831845f   // 1/sqrt(128)

// ---------------------------------------------------------------------------
// Scratch
// ---------------------------------------------------------------------------
__device__ float g_q[B_ * NH_ * S_ * HD_];   // [bh][s][d] (pre-scaled)
__device__ float g_k[B_ * NH_ * S_ * HD_];
__device__ float g_v[B_ * NH_ * S_ * HD_];
__device__ float g_ctx[BS_ * DM_];
__device__ float g_cos[S_ * (HD_ / 2)];
__device__ float g_sin[S_ * (HD_ / 2)];

// ---------------------------------------------------------------------------
// RoPE table (double precision)
// ---------------------------------------------------------------------------
__global__ void rope_table_kernel() {
    int idx = blockIdx.x * blockDim.x + threadIdx.x;
    if (idx >= S_ * (HD_ / 2)) return;
    int s = idx / (HD_ / 2);
    int i = idx % (HD_ / 2);
    double inv_freq = exp(-((double)(2 * i) / (double)HD_) * log(10000.0));
    double ang = (double)s * inv_freq;
    g_cos[idx] = (float)cos(ang);
    g_sin[idx] = (float)sin(ang);
}

__device__ __forceinline__ unsigned f2tf32(float x) {
    unsigned r;
    asm("cvt.rna.tf32.f32 %0, %1;" : "=r"(r) : "f"(x));
    return r;
}

#define MMA_TF32(C, a0, a1, a2, a3, b0, b1)                                   \
    asm volatile(                                                             \
        "mma.sync.aligned.m16n8k8.row.col.f32.tf32.tf32.f32 "                 \
        "{%0,%1,%2,%3}, {%4,%5,%6,%7}, {%8,%9}, {%0,%1,%2,%3};"               \
        : "+f"((C)[0]), "+f"((C)[1]), "+f"((C)[2]), "+f"((C)[3])              \
        : "r"(a0), "r"(a1), "r"(a2), "r"(a3), "r"(b0), "r"(b1))

// ---------------------------------------------------------------------------
// TF32 GEMM, double-buffered smem, one sync per 32-k block.
// mode 0: rope+scale+scatter (Q)   mode 3: rope+scatter (K)
// mode 1: scatter (V)              mode 2: row-major write (O proj)
// mode0 < 0 -> derive from blockIdx.z (merged QKV launch)
// ---------------------------------------------------------------------------
#define GK 2048
#define GN 2048
#define SMS 136
#define ABUF (32 * SMS)               // 4352 words per stage

__global__ __launch_bounds__(256) void tgemm_kernel(
    const float* __restrict__ A,
    const float* __restrict__ W0, const float* __restrict__ W1,
    const float* __restrict__ W2,
    const float* __restrict__ b0p, const float* __restrict__ b1p,
    const float* __restrict__ b2p,
    float* __restrict__ C0, float* __restrict__ C1, float* __restrict__ C2,
    int mode0)
{
    extern __shared__ unsigned dsm[];   // As[2][32][SMS], Bs[2][32][SMS]

    const float* W; const float* bias; float* C; int mode;
    if (mode0 >= 0) { W = W0; bias = b0p; C = C0; mode = mode0; }
    else {
        const int z = blockIdx.z;
        W    = (z == 0) ? W0 : (z == 1) ? W1 : W2;
        bias = (z == 0) ? b0p : (z == 1) ? b1p : b2p;
        C    = (z == 0) ? C0 : (z == 1) ? C1 : C2;
        mode = (z == 0) ? 0 : (z == 1) ? 3 : 1;
    }

    const int tid  = threadIdx.x;
    const int lane = tid & 31, wid = tid >> 5;
    const int warpM = wid >> 2, warpN = wid & 3;
    const int gid = lane >> 2, tig = lane & 3;
    const int m0 = blockIdx.y * 128, n0 = blockIdx.x * 128;

    const int am  = tid & 127;
    const int akq = tid >> 7;
    const int bn  = (tid & 31) * 4;
    const int bk  = tid >> 5;

    const float* Ap = A + (size_t)(m0 + am) * GK + akq * 16;
    const float* Wp = W + (size_t)bk * GN + n0 + bn;

    float acc[4][4][4];
    #pragma unroll
    for (int mi = 0; mi < 4; mi++)
        #pragma unroll
        for (int ni = 0; ni < 4; ni++)
            #pragma unroll
            for (int u = 0; u < 4; u++) acc[mi][ni][u] = 0.f;

    float4 ra[4], rb[4];
    #pragma unroll
    for (int j = 0; j < 4; j++) ra[j] = *(const float4*)(Ap + j * 4);
    #pragma unroll
    for (int j = 0; j < 4; j++) rb[j] = *(const float4*)(Wp + (size_t)(j * 8) * GN);

    int p = 0;
    for (int kb = 0; kb < GK; kb += 32, p ^= 1) {
        unsigned* As = dsm + p * ABUF;
        unsigned* Bs = dsm + 2 * ABUF + p * ABUF;

        // stage current regs -> smem buffer p
        #pragma unroll
        for (int j = 0; j < 4; j++) {
            int k = akq * 16 + j * 4;
            As[(k + 0) * SMS + am] = f2tf32(ra[j].x);
            As[(k + 1) * SMS + am] = f2tf32(ra[j].y);
            As[(k + 2) * SMS + am] = f2tf32(ra[j].z);
            As[(k + 3) * SMS + am] = f2tf32(ra[j].w);
        }
        #pragma unroll
        for (int j = 0; j < 4; j++) {
            uint4 t;
            t.x = f2tf32(rb[j].x); t.y = f2tf32(rb[j].y);
            t.z = f2tf32(rb[j].z); t.w = f2tf32(rb[j].w);
            *(uint4*)&Bs[(bk + j * 8) * SMS + bn] = t;
        }
        __syncthreads();

        // prefetch next tile (overlaps MMAs)
        if (kb + 32 < GK) {
            #pragma unroll
            for (int j = 0; j < 4; j++)
                ra[j] = *(const float4*)(Ap + kb + 32 + j * 4);
            #pragma unroll
            for (int j = 0; j < 4; j++)
                rb[j] = *(const float4*)(Wp + (size_t)(kb + 32 + j * 8) * GN);
        }

        #pragma unroll
        for (int kk = 0; kk < 32; kk += 8) {
            unsigned af[4][4], bf[4][2];
            #pragma unroll
            for (int mi = 0; mi < 4; mi++) {
                int mr = warpM * 64 + mi * 16 + gid;
                af[mi][0] = As[(kk + tig) * SMS + mr];
                af[mi][1] = As[(kk + tig) * SMS + mr + 8];
                af[mi][2] = As[(kk + tig + 4) * SMS + mr];
                af[mi][3] = As[(kk + tig + 4) * SMS + mr + 8];
            }
            #pragma unroll
            for (int ni = 0; ni < 4; ni++) {
                int nc = warpN * 32 + ni * 8 + gid;
                bf[ni][0] = Bs[(kk + tig) * SMS + nc];
                bf[ni][1] = Bs[(kk + tig + 4) * SMS + nc];
            }
            #pragma unroll
            for (int mi = 0; mi < 4; mi++)
                #pragma unroll
                for (int ni = 0; ni < 4; ni++)
                    MMA_TF32(acc[mi][ni], af[mi][0], af[mi][1], af[mi][2],
                             af[mi][3], bf[ni][0], bf[ni][1]);
        }
        // no trailing sync: next iteration's STS targets the other buffer,
        // and the sync inside iteration i+1 orders reads(i) vs writes(i+2).
    }

    // Epilogue: bias (+ RoPE) (+ scale) (+ scatter)
    #pragma unroll
    for (int ni = 0; ni < 4; ni++) {
        const int c = n0 + warpN * 32 + ni * 8 + tig * 2;
        const float bv0 = bias[c], bv1 = bias[c + 1];
        #pragma unroll
        for (int mi = 0; mi < 4; mi++) {
            #pragma unroll
            for (int half = 0; half < 2; half++) {
                const int r = m0 + warpM * 64 + mi * 16 + gid + half * 8;
                float v0 = acc[mi][ni][half * 2 + 0] + bv0;
                float v1 = acc[mi][ni][half * 2 + 1] + bv1;
                const int bb = r >> 11;
                const int s  = r & (S_ - 1);
                if (mode == 0 || mode == 3) {
                    const int pi = (c & (HD_ - 1)) >> 1;
                    const float cs = g_cos[s * (HD_ / 2) + pi];
                    const float sn = g_sin[s * (HD_ / 2) + pi];
                    const float e = v0, o = v1;
                    v0 = e * cs - o * sn;
                    v1 = o * cs + e * sn;
                    if (mode == 0) { v0 *= SCALE_; v1 *= SCALE_; }
                }
                float2 val; val.x = v0; val.y = v1;
                if (mode != 2) {
                    const int h = (c >> 7) & (NH_ - 1);
                    const int d = c & (HD_ - 1);
                    *(float2*)(C + (size_t)((bb * NH_ + h) * S_ + s) * HD_ + d) = val;
                } else {
                    *(float2*)(C + (size_t)r * GN + c) = val;
                }
            }
        }
    }
}

// ---------------------------------------------------------------------------
// Flash attention (causal) on tf32 tensor cores (unchanged from R3).
// ---------------------------------------------------------------------------
#define AST 132

__global__ __launch_bounds__(128) void attn_mma_kernel(
    const float* __restrict__ q, const float* __restrict__ k,
    const float* __restrict__ v, float* __restrict__ ctx)
{
    extern __shared__ unsigned smu[];
    unsigned* Qs = smu;
    unsigned* Ks = Qs + 64 * AST;
    unsigned* Vs = Ks + 64 * AST;

    const int tid  = threadIdx.x;
    const int lane = tid & 31, wid = tid >> 5;
    const int gid = lane >> 2, tig = lane & 3;
    const int bh = blockIdx.y;
    const int qt = gridDim.x - 1 - blockIdx.x;
    const int q0 = qt * 64;
    const int m0w = wid * 16;

    const float* qp = q + ((size_t)bh * S_ + q0) * HD_;
    const float* kb = k + (size_t)bh * S_ * HD_;
    const float* vb = v + (size_t)bh * S_ * HD_;

    for (int t = tid; t < 64 * 32; t += 128) {
        int r = t >> 5, c = (t & 31) * 4;
        float4 f = *(const float4*)&qp[r * HD_ + c];
        uint4 u;
        u.x = f2tf32(f.x); u.y = f2tf32(f.y);
        u.z = f2tf32(f.z); u.w = f2tf32(f.w);
        *(uint4*)&Qs[r * AST + c] = u;
    }

    float oacc[16][4];
    #pragma unroll
    for (int ni = 0; ni < 16; ni++)
        #pragma unroll
        for (int u = 0; u < 4; u++) oacc[ni][u] = 0.f;
    float mx0 = -1e30f, mx1 = -1e30f, ls0 = 0.f, ls1 = 0.f;

    const int nkv = qt + 1;
    for (int kt = 0; kt < nkv; kt++) {
        const int k0 = kt * 64;
        __syncthreads();
        const float* kp = kb + (size_t)k0 * HD_;
        const float* vp = vb + (size_t)k0 * HD_;
        for (int t = tid; t < 64 * 32; t += 128) {
            int r = t >> 5, c = (t & 31) * 4;
            float4 fk = *(const float4*)&kp[r * HD_ + c];
            float4 fv = *(const float4*)&vp[r * HD_ + c];
            uint4 uk, uv;
            uk.x = f2tf32(fk.x); uk.y = f2tf32(fk.y);
            uk.z = f2tf32(fk.z); uk.w = f2tf32(fk.w);
            uv.x = f2tf32(fv.x); uv.y = f2tf32(fv.y);
            uv.z = f2tf32(fv.z); uv.w = f2tf32(fv.w);
            *(uint4*)&Ks[r * AST + c] = uk;
            *(uint4*)&Vs[r * AST + c] = uv;
        }
        __syncthreads();

        float sacc[8][4];
        #pragma unroll
        for (int ni = 0; ni < 8; ni++)
            #pragma unroll
            for (int u = 0; u < 4; u++) sacc[ni][u] = 0.f;

        #pragma unroll
        for (int ks = 0; ks < 16; ks++) {
            const int kk = ks * 8;
            unsigned a0 = Qs[(m0w + gid) * AST + kk + tig];
            unsigned a1 = Qs[(m0w + gid + 8) * AST + kk + tig];
            unsigned a2 = Qs[(m0w + gid) * AST + kk + tig + 4];
            unsigned a3 = Qs[(m0w + gid + 8) * AST + kk + tig + 4];
            #pragma unroll
            for (int ni = 0; ni < 8; ni++) {
                unsigned b0 = Ks[(ni * 8 + gid) * AST + kk + tig];
                unsigned b1 = Ks[(ni * 8 + gid) * AST + kk + tig + 4];
                MMA_TF32(sacc[ni], a0, a1, a2, a3, b0, b1);
            }
        }

        if (kt == nkv - 1) {
            const int row0 = q0 + m0w + gid;
            #pragma unroll
            for (int ni = 0; ni < 8; ni++) {
                const int col = k0 + ni * 8 + tig * 2;
                if (col > row0)     sacc[ni][0] = -1e30f;
                if (col + 1 > row0) sacc[ni][1] = -1e30f;
                if (col > row0 + 8)     sacc[ni][2] = -1e30f;
                if (col + 1 > row0 + 8) sacc[ni][3] = -1e30f;
            }
        }

        float rm0 = -1e30f, rm1 = -1e30f;
        #pragma unroll
        for (int ni = 0; ni < 8; ni++) {
            rm0 = fmaxf(rm0, fmaxf(sacc[ni][0], sacc[ni][1]));
            rm1 = fmaxf(rm1, fmaxf(sacc[ni][2], sacc[ni][3]));
        }
        rm0 = fmaxf(rm0, __shfl_xor_sync(0xffffffffu, rm0, 1));
        rm0 = fmaxf(rm0, __shfl_xor_sync(0xffffffffu, rm0, 2));
        rm1 = fmaxf(rm1, __shfl_xor_sync(0xffffffffu, rm1, 1));
        rm1 = fmaxf(rm1, __shfl_xor_sync(0xffffffffu, rm1, 2));

        const float mn0 = fmaxf(mx0, rm0), mn1 = fmaxf(mx1, rm1);
        const float f0 = __expf(mx0 - mn0), f1 = __expf(mx1 - mn1);
        float rs0 = 0.f, rs1 = 0.f;
        #pragma unroll
        for (int ni = 0; ni < 8; ni++) {
            float p0 = __expf(sacc[ni][0] - mn0);
            float p1 = __expf(sacc[ni][1] - mn0);
            float p2 = __expf(sacc[ni][2] - mn1);
            float p3 = __expf(sacc[ni][3] - mn1);
            sacc[ni][0] = p0; sacc[ni][1] = p1;
            sacc[ni][2] = p2; sacc[ni][3] = p3;
            rs0 += p0 + p1; rs1 += p2 + p3;
        }
        rs0 += __shfl_xor_sync(0xffffffffu, rs0, 1);
        rs0 += __shfl_xor_sync(0xffffffffu, rs0, 2);
        rs1 += __shfl_xor_sync(0xffffffffu, rs1, 1);
        rs1 += __shfl_xor_sync(0xffffffffu, rs1, 2);
        ls0 = ls0 * f0 + rs0; ls1 = ls1 * f1 + rs1;
        mx0 = mn0; mx1 = mn1;

        #pragma unroll
        for (int ni = 0; ni < 16; ni++) {
            oacc[ni][0] *= f0; oacc[ni][1] *= f0;
            oacc[ni][2] *= f1; oacc[ni][3] *= f1;
        }

        #pragma unroll
        for (int kk = 0; kk < 8; kk++) {
            const int l1 = (gid << 2) | (tig >> 1);
            const int l2 = l1 + 2;
            float v00 = __shfl_sync(0xffffffffu, sacc[kk][0], l1);
            float v01 = __shfl_sync(0xffffffffu, sacc[kk][1], l1);
            float v10 = __shfl_sync(0xffffffffu, sacc[kk][2], l1);
            float v11 = __shfl_sync(0xffffffffu, sacc[kk][3], l1);
            float w00 = __shfl_sync(0xffffffffu, sacc[kk][0], l2);
            float w01 = __shfl_sync(0xffffffffu, sacc[kk][1], l2);
            float w10 = __shfl_sync(0xffffffffu, sacc[kk][2], l2);
            float w11 = __shfl_sync(0xffffffffu, sacc[kk][3], l2);
            const bool odd = tig & 1;
            unsigned pa0 = f2tf32(odd ? v01 : v00);
            unsigned pa1 = f2tf32(odd ? v11 : v10);
            unsigned pa2 = f2tf32(odd ? w01 : w00);
            unsigned pa3 = f2tf32(odd ? w11 : w10);
            #pragma unroll
            for (int ni = 0; ni < 16; ni++) {
                unsigned b0 = Vs[(kk * 8 + tig) * AST + ni * 8 + gid];
                unsigned b1 = Vs[(kk * 8 + tig + 4) * AST + ni * 8 + gid];
                MMA_TF32(oacc[ni], pa0, pa1, pa2, pa3, b0, b1);
            }
        }
    }

    const float inv0 = 1.f / ls0, inv1 = 1.f / ls1;
    const int b = bh >> 4, h = bh & 15;
    const int s0 = q0 + m0w + gid;
    #pragma unroll
    for (int ni = 0; ni < 16; ni++) {
        const int col = ni * 8 + tig * 2;
        float2 r0; r0.x = oacc[ni][0] * inv0; r0.y = oacc[ni][1] * inv0;
        float2 r1; r1.x = oacc[ni][2] * inv1; r1.y = oacc[ni][3] * inv1;
        *(float2*)(ctx + (size_t)(b * S_ + s0) * DM_ + h * HD_ + col) = r0;
        *(float2*)(ctx + (size_t)(b * S_ + s0 + 8) * DM_ + h * HD_ + col) = r1;
    }
}

// ---------------------------------------------------------------------------
// Launch
// ---------------------------------------------------------------------------
extern "C" void kernel_launch(void* const* d_in, const int* in_sizes, int n_in,
                              void* d_out, int out_size)
{
    const float* hs = (const float*)d_in[0];
    const float* Wq = (const float*)d_in[1];
    const float* bq = (const float*)d_in[2];
    const float* Wk = (const float*)d_in[3];
    const float* bk = (const float*)d_in[4];
    const float* Wv = (const float*)d_in[5];
    const float* bv = (const float*)d_in[6];
    const float* Wo = (const float*)d_in[7];
    const float* bo = (const float*)d_in[8];
    float* out = (float*)d_out;

    float *qd, *kd, *vd, *ctxd;
    cudaGetSymbolAddress((void**)&qd,   g_q);
    cudaGetSymbolAddress((void**)&kd,   g_k);
    cudaGetSymbolAddress((void**)&vd,   g_v);
    cudaGetSymbolAddress((void**)&ctxd, g_ctx);

    const int gemm_smem = 4 * ABUF * (int)sizeof(unsigned);   // 69632 B
    const int attn_smem = 3 * 64 * AST * (int)sizeof(unsigned);
    static int smem_set = 0;
    if (!smem_set) {
        cudaFuncSetAttribute(tgemm_kernel,
                             cudaFuncAttributeMaxDynamicSharedMemorySize,
                             gemm_smem);
        cudaFuncSetAttribute(attn_mma_kernel,
                             cudaFuncAttributeMaxDynamicSharedMemorySize,
                             attn_smem);
        smem_set = 1;
    }

    rope_table_kernel<<<(S_ * (HD_ / 2) + 255) / 256, 256>>>();

    // Merged QKV: z=0 -> Q(mode0), z=1 -> K(mode3), z=2 -> V(mode1)
    dim3 qkvgrid(GN / 128, 4096 / 128, 3);
    tgemm_kernel<<<qkvgrid, 256, gemm_smem>>>(
        hs, Wq, Wk, Wv, bq, bk, bv, qd, kd, vd, -1);

    dim3 agrid(S_ / 64, B_ * NH_);
    attn_mma_kernel<<<agrid, 128, attn_smem>>>(qd, kd, vd, ctxd);

    dim3 ogrid(GN / 128, 4096 / 128, 1);
    tgemm_kernel<<<ogrid, 256, gemm_smem>>>(
        ctxd, Wo, nullptr, nullptr, bo, nullptr, nullptr, out, nullptr,
        nullptr, 2);
}

// round 6
// speedup vs baseline: 1.0150x; 1.0150x over previous
#include <cuda_runtime.h>
#include <cuda_bf16.h>
#include <math.h>
#include <stdint.h>

// Problem constants
#define B_  2
#define S_  2048
#define DM_ 2048
#define NH_ 16
#define HD_ 128
#define BS_ (B_ * S_)
#define SCALE_ 0.08838834764831845f   // 1/sqrt(128)
#define GK 2048
#define GN 2048

// ---------------------------------------------------------------------------
// Scratch
// ---------------------------------------------------------------------------
__device__ float g_q[B_ * NH_ * S_ * HD_];   // [bh][s][d] (pre-scaled)
__device__ float g_k[B_ * NH_ * S_ * HD_];
__device__ float g_v[B_ * NH_ * S_ * HD_];
__device__ float g_ctx[BS_ * DM_];           // tf32-rounded by attention
__device__ float g_hst[BS_ * DM_];           // tf32-rounded hidden states
__device__ float g_wc[4][DM_ * DM_];         // tf32-rounded Wq,Wk,Wv,Wo
__device__ float g_cos[S_ * (HD_ / 2)];
__device__ float g_sin[S_ * (HD_ / 2)];

// ---------------------------------------------------------------------------
// RoPE table (double precision)
// ---------------------------------------------------------------------------
__global__ void rope_table_kernel() {
    int idx = blockIdx.x * blockDim.x + threadIdx.x;
    if (idx >= S_ * (HD_ / 2)) return;
    int s = idx / (HD_ / 2);
    int i = idx % (HD_ / 2);
    double inv_freq = exp(-((double)(2 * i) / (double)HD_) * log(10000.0));
    double ang = (double)s * inv_freq;
    g_cos[idx] = (float)cos(ang);
    g_sin[idx] = (float)sin(ang);
}

__device__ __forceinline__ unsigned f2tf32(float x) {
    unsigned r;
    asm("cvt.rna.tf32.f32 %0, %1;" : "=r"(r) : "f"(x));
    return r;
}

// tf32-round prepass (float4 grid-stride)
__global__ void cvt_kernel(const float* __restrict__ in,
                           float* __restrict__ out, int n4) {
    int i = blockIdx.x * blockDim.x + threadIdx.x;
    if (i >= n4) return;
    float4 f = ((const float4*)in)[i];
    uint4 u;
    u.x = f2tf32(f.x); u.y = f2tf32(f.y);
    u.z = f2tf32(f.z); u.w = f2tf32(f.w);
    ((uint4*)out)[i] = u;
}

__device__ __forceinline__ uint32_t smem_u32(const void* p) {
    uint32_t a;
    asm("{ .reg .u64 t; cvta.to.shared.u64 t, %1; cvt.u32.u64 %0, t; }"
        : "=r"(a) : "l"(p));
    return a;
}

#define CP_ASYNC16(dst, src)                                                  \
    asm volatile("cp.async.cg.shared.global [%0], [%1], 16;"                  \
                 :: "r"(dst), "l"(src) : "memory")

#define MMA_TF32(Cc, a0, a1, a2, a3, b0, b1)                                  \
    asm volatile(                                                             \
        "mma.sync.aligned.m16n8k8.row.col.f32.tf32.tf32.f32 "                 \
        "{%0,%1,%2,%3}, {%4,%5,%6,%7}, {%8,%9}, {%0,%1,%2,%3};"               \
        : "+f"((Cc)[0]), "+f"((Cc)[1]), "+f"((Cc)[2]), "+f"((Cc)[3])          \
        : "r"(a0), "r"(a1), "r"(a2), "r"(a3), "r"(b0), "r"(b1))

// ---------------------------------------------------------------------------
// TF32 GEMM: 128x128 CTA tile, 128 threads (4 warps of 64x64), BK=32,
// cp.async 3-stage pipeline. Inputs must be pre-rounded to tf32.
// As [m][k] stride 36 words; Bs [k][n] stride 136 words (both conflict-free).
// mode 0: rope+scale+scatter (Q)  mode 3: rope+scatter (K)
// mode 1: scatter (V)             mode 2: row-major (O proj)
// mode0 < 0: derive from blockIdx.z (merged QKV).
// ---------------------------------------------------------------------------
#define NKB (GK / 32)
#define A_BYTES 18432                 // 128*36*4
#define STAGEB  35840                 // A_BYTES + 32*136*4

__global__ __launch_bounds__(128, 2) void tc2_gemm(
    const float* __restrict__ A,
    const float* __restrict__ W0, const float* __restrict__ W1,
    const float* __restrict__ W2,
    const float* __restrict__ b0p, const float* __restrict__ b1p,
    const float* __restrict__ b2p,
    float* __restrict__ C0, float* __restrict__ C1, float* __restrict__ C2,
    int mode0)
{
    extern __shared__ unsigned char smraw[];

    const float* W; const float* bias; float* C; int mode;
    if (mode0 >= 0) { W = W0; bias = b0p; C = C0; mode = mode0; }
    else {
        const int z = blockIdx.z;
        W    = (z == 0) ? W0 : (z == 1) ? W1 : W2;
        bias = (z == 0) ? b0p : (z == 1) ? b1p : b2p;
        C    = (z == 0) ? C0 : (z == 1) ? C1 : C2;
        mode = (z == 0) ? 0 : (z == 1) ? 3 : 1;
    }

    const int tid = threadIdx.x;
    const int lane = tid & 31, wid = tid >> 5;
    const int wm = wid >> 1, wn = wid & 1;
    const int gid = lane >> 2, tig = lane & 3;
    const int m0 = blockIdx.y * 128, n0 = blockIdx.x * 128;

    const uint32_t sb = smem_u32(smraw);

    // cp.async source/dest assignments
    const float* Asrc = A + (size_t)(m0 + tid) * GK;       // one m-row/thread
    const int kr   = tid >> 2;                             // B k-row 0..31
    const int nseg = (tid & 3) * 32;                       // B n-segment
    const float* Bsrc = W + (size_t)kr * GN + n0 + nseg;

    auto issue = [&](int ib) {
        const int p = ib % 3;
        const uint32_t ab = sb + p * STAGEB;
        const uint32_t bb = ab + A_BYTES;
        const float* as = Asrc + ib * 32;
        #pragma unroll
        for (int j = 0; j < 8; j++)
            CP_ASYNC16(ab + tid * 144 + j * 16, as + j * 4);
        const float* bs = Bsrc + (size_t)(ib * 32) * GN;
        #pragma unroll
        for (int j = 0; j < 8; j++)
            CP_ASYNC16(bb + kr * 544 + nseg * 4 + j * 16, bs + j * 4);
        asm volatile("cp.async.commit_group;" ::: "memory");
    };
    issue(0);
    issue(1);

    float acc[4][8][4];
    #pragma unroll
    for (int mi = 0; mi < 4; mi++)
        #pragma unroll
        for (int ni = 0; ni < 8; ni++)
            #pragma unroll
            for (int u = 0; u < 4; u++) acc[mi][ni][u] = 0.f;

    for (int ib = 0; ib < NKB; ib++) {
        if (ib + 1 < NKB)
            asm volatile("cp.async.wait_group 1;" ::: "memory");
        else
            asm volatile("cp.async.wait_group 0;" ::: "memory");
        __syncthreads();
        if (ib + 2 < NKB) issue(ib + 2);

        const unsigned* As = (const unsigned*)(smraw + (ib % 3) * STAGEB);
        const unsigned* Bs = (const unsigned*)(smraw + (ib % 3) * STAGEB + A_BYTES);

        #pragma unroll
        for (int kk = 0; kk < 32; kk += 8) {
            unsigned af[4][4], bf[8][2];
            #pragma unroll
            for (int mi = 0; mi < 4; mi++) {
                const int mrow = wm * 64 + mi * 16 + gid;
                af[mi][0] = As[mrow * 36 + kk + tig];
                af[mi][1] = As[(mrow + 8) * 36 + kk + tig];
                af[mi][2] = As[mrow * 36 + kk + tig + 4];
                af[mi][3] = As[(mrow + 8) * 36 + kk + tig + 4];
            }
            #pragma unroll
            for (int ni = 0; ni < 8; ni++) {
                const int nc = wn * 64 + ni * 8 + gid;
                bf[ni][0] = Bs[(kk + tig) * 136 + nc];
                bf[ni][1] = Bs[(kk + tig + 4) * 136 + nc];
            }
            #pragma unroll
            for (int mi = 0; mi < 4; mi++)
                #pragma unroll
                for (int ni = 0; ni < 8; ni++)
                    MMA_TF32(acc[mi][ni], af[mi][0], af[mi][1], af[mi][2],
                             af[mi][3], bf[ni][0], bf[ni][1]);
        }
    }

    // Epilogue: bias (+ RoPE) (+ scale) (+ scatter)
    #pragma unroll
    for (int ni = 0; ni < 8; ni++) {
        const int c = n0 + wn * 64 + ni * 8 + tig * 2;
        const float bv0 = bias[c], bv1 = bias[c + 1];
        #pragma unroll
        for (int mi = 0; mi < 4; mi++) {
            #pragma unroll
            for (int half = 0; half < 2; half++) {
                const int r = m0 + wm * 64 + mi * 16 + gid + half * 8;
                float v0 = acc[mi][ni][half * 2 + 0] + bv0;
                float v1 = acc[mi][ni][half * 2 + 1] + bv1;
                const int bb = r >> 11;
                const int s  = r & (S_ - 1);
                if (mode == 0 || mode == 3) {
                    const int pi = (c & (HD_ - 1)) >> 1;
                    const float cs = g_cos[s * (HD_ / 2) + pi];
                    const float sn = g_sin[s * (HD_ / 2) + pi];
                    const float e = v0, o = v1;
                    v0 = e * cs - o * sn;
                    v1 = o * cs + e * sn;
                    if (mode == 0) { v0 *= SCALE_; v1 *= SCALE_; }
                }
                float2 val; val.x = v0; val.y = v1;
                if (mode != 2) {
                    const int h = (c >> 7) & (NH_ - 1);
                    const int d = c & (HD_ - 1);
                    *(float2*)(C + (size_t)((bb * NH_ + h) * S_ + s) * HD_ + d) = val;
                } else {
                    *(float2*)(C + (size_t)r * GN + c) = val;
                }
            }
        }
    }
}

// ---------------------------------------------------------------------------
// Flash attention (causal) on tf32 mma.sync (R3-proven; ctx written
// tf32-rounded so the O-projection can cp.async it directly).
// ---------------------------------------------------------------------------
#define AST 132

__global__ __launch_bounds__(128) void attn_mma_kernel(
    const float* __restrict__ q, const float* __restrict__ k,
    const float* __restrict__ v, float* __restrict__ ctx)
{
    extern __shared__ unsigned smu[];
    unsigned* Qs = smu;
    unsigned* Ks = Qs + 64 * AST;
    unsigned* Vs = Ks + 64 * AST;

    const int tid  = threadIdx.x;
    const int lane = tid & 31, wid = tid >> 5;
    const int gid = lane >> 2, tig = lane & 3;
    const int bh = blockIdx.y;
    const int qt = gridDim.x - 1 - blockIdx.x;
    const int q0 = qt * 64;
    const int m0w = wid * 16;

    const float* qp = q + ((size_t)bh * S_ + q0) * HD_;
    const float* kb = k + (size_t)bh * S_ * HD_;
    const float* vb = v + (size_t)bh * S_ * HD_;

    for (int t = tid; t < 64 * 32; t += 128) {
        int r = t >> 5, c = (t & 31) * 4;
        float4 f = *(const float4*)&qp[r * HD_ + c];
        uint4 u;
        u.x = f2tf32(f.x); u.y = f2tf32(f.y);
        u.z = f2tf32(f.z); u.w = f2tf32(f.w);
        *(uint4*)&Qs[r * AST + c] = u;
    }

    float oacc[16][4];
    #pragma unroll
    for (int ni = 0; ni < 16; ni++)
        #pragma unroll
        for (int u = 0; u < 4; u++) oacc[ni][u] = 0.f;
    float mx0 = -1e30f, mx1 = -1e30f, ls0 = 0.f, ls1 = 0.f;

    const int nkv = qt + 1;
    for (int kt = 0; kt < nkv; kt++) {
        const int k0 = kt * 64;
        __syncthreads();
        const float* kp = kb + (size_t)k0 * HD_;
        const float* vp = vb + (size_t)k0 * HD_;
        for (int t = tid; t < 64 * 32; t += 128) {
            int r = t >> 5, c = (t & 31) * 4;
            float4 fk = *(const float4*)&kp[r * HD_ + c];
            float4 fv = *(const float4*)&vp[r * HD_ + c];
            uint4 uk, uv;
            uk.x = f2tf32(fk.x); uk.y = f2tf32(fk.y);
            uk.z = f2tf32(fk.z); uk.w = f2tf32(fk.w);
            uv.x = f2tf32(fv.x); uv.y = f2tf32(fv.y);
            uv.z = f2tf32(fv.z); uv.w = f2tf32(fv.w);
            *(uint4*)&Ks[r * AST + c] = uk;
            *(uint4*)&Vs[r * AST + c] = uv;
        }
        __syncthreads();

        float sacc[8][4];
        #pragma unroll
        for (int ni = 0; ni < 8; ni++)
            #pragma unroll
            for (int u = 0; u < 4; u++) sacc[ni][u] = 0.f;

        #pragma unroll
        for (int ks = 0; ks < 16; ks++) {
            const int kk = ks * 8;
            unsigned a0 = Qs[(m0w + gid) * AST + kk + tig];
            unsigned a1 = Qs[(m0w + gid + 8) * AST + kk + tig];
            unsigned a2 = Qs[(m0w + gid) * AST + kk + tig + 4];
            unsigned a3 = Qs[(m0w + gid + 8) * AST + kk + tig + 4];
            #pragma unroll
            for (int ni = 0; ni < 8; ni++) {
                unsigned b0 = Ks[(ni * 8 + gid) * AST + kk + tig];
                unsigned b1 = Ks[(ni * 8 + gid) * AST + kk + tig + 4];
                MMA_TF32(sacc[ni], a0, a1, a2, a3, b0, b1);
            }
        }

        if (kt == nkv - 1) {
            const int row0 = q0 + m0w + gid;
            #pragma unroll
            for (int ni = 0; ni < 8; ni++) {
                const int col = k0 + ni * 8 + tig * 2;
                if (col > row0)     sacc[ni][0] = -1e30f;
                if (col + 1 > row0) sacc[ni][1] = -1e30f;
                if (col > row0 + 8)     sacc[ni][2] = -1e30f;
                if (col + 1 > row0 + 8) sacc[ni][3] = -1e30f;
            }
        }

        float rm0 = -1e30f, rm1 = -1e30f;
        #pragma unroll
        for (int ni = 0; ni < 8; ni++) {
            rm0 = fmaxf(rm0, fmaxf(sacc[ni][0], sacc[ni][1]));
            rm1 = fmaxf(rm1, fmaxf(sacc[ni][2], sacc[ni][3]));
        }
        rm0 = fmaxf(rm0, __shfl_xor_sync(0xffffffffu, rm0, 1));
        rm0 = fmaxf(rm0, __shfl_xor_sync(0xffffffffu, rm0, 2));
        rm1 = fmaxf(rm1, __shfl_xor_sync(0xffffffffu, rm1, 1));
        rm1 = fmaxf(rm1, __shfl_xor_sync(0xffffffffu, rm1, 2));

        const float mn0 = fmaxf(mx0, rm0), mn1 = fmaxf(mx1, rm1);
        const float f0 = __expf(mx0 - mn0), f1 = __expf(mx1 - mn1);
        float rs0 = 0.f, rs1 = 0.f;
        #pragma unroll
        for (int ni = 0; ni < 8; ni++) {
            float p0 = __expf(sacc[ni][0] - mn0);
            float p1 = __expf(sacc[ni][1] - mn0);
            float p2 = __expf(sacc[ni][2] - mn1);
            float p3 = __expf(sacc[ni][3] - mn1);
            sacc[ni][0] = p0; sacc[ni][1] = p1;
            sacc[ni][2] = p2; sacc[ni][3] = p3;
            rs0 += p0 + p1; rs1 += p2 + p3;
        }
        rs0 += __shfl_xor_sync(0xffffffffu, rs0, 1);
        rs0 += __shfl_xor_sync(0xffffffffu, rs0, 2);
        rs1 += __shfl_xor_sync(0xffffffffu, rs1, 1);
        rs1 += __shfl_xor_sync(0xffffffffu, rs1, 2);
        ls0 = ls0 * f0 + rs0; ls1 = ls1 * f1 + rs1;
        mx0 = mn0; mx1 = mn1;

        #pragma unroll
        for (int ni = 0; ni < 16; ni++) {
            oacc[ni][0] *= f0; oacc[ni][1] *= f0;
            oacc[ni][2] *= f1; oacc[ni][3] *= f1;
        }

        #pragma unroll
        for (int kk = 0; kk < 8; kk++) {
            const int l1 = (gid << 2) | (tig >> 1);
            const int l2 = l1 + 2;
            float v00 = __shfl_sync(0xffffffffu, sacc[kk][0], l1);
            float v01 = __shfl_sync(0xffffffffu, sacc[kk][1], l1);
            float v10 = __shfl_sync(0xffffffffu, sacc[kk][2], l1);
            float v11 = __shfl_sync(0xffffffffu, sacc[kk][3], l1);
            float w00 = __shfl_sync(0xffffffffu, sacc[kk][0], l2);
            float w01 = __shfl_sync(0xffffffffu, sacc[kk][1], l2);
            float w10 = __shfl_sync(0xffffffffu, sacc[kk][2], l2);
            float w11 = __shfl_sync(0xffffffffu, sacc[kk][3], l2);
            const bool odd = tig & 1;
            unsigned pa0 = f2tf32(odd ? v01 : v00);
            unsigned pa1 = f2tf32(odd ? v11 : v10);
            unsigned pa2 = f2tf32(odd ? w01 : w00);
            unsigned pa3 = f2tf32(odd ? w11 : w10);
            #pragma unroll
            for (int ni = 0; ni < 16; ni++) {
                unsigned b0 = Vs[(kk * 8 + tig) * AST + ni * 8 + gid];
                unsigned b1 = Vs[(kk * 8 + tig + 4) * AST + ni * 8 + gid];
                MMA_TF32(oacc[ni], pa0, pa1, pa2, pa3, b0, b1);
            }
        }
    }

    const float inv0 = 1.f / ls0, inv1 = 1.f / ls1;
    const int b = bh >> 4, h = bh & 15;
    const int s0 = q0 + m0w + gid;
    #pragma unroll
    for (int ni = 0; ni < 16; ni++) {
        const int col = ni * 8 + tig * 2;
        // tf32-round ctx so O-proj can cp.async it without conversion
        float2 r0, r1;
        r0.x = __uint_as_float(f2tf32(oacc[ni][0] * inv0));
        r0.y = __uint_as_float(f2tf32(oacc[ni][1] * inv0));
        r1.x = __uint_as_float(f2tf32(oacc[ni][2] * inv1));
        r1.y = __uint_as_float(f2tf32(oacc[ni][3] * inv1));
        *(float2*)(ctx + (size_t)(b * S_ + s0) * DM_ + h * HD_ + col) = r0;
        *(float2*)(ctx + (size_t)(b * S_ + s0 + 8) * DM_ + h * HD_ + col) = r1;
    }
}

// ---------------------------------------------------------------------------
// Launch
// ---------------------------------------------------------------------------
extern "C" void kernel_launch(void* const* d_in, const int* in_sizes, int n_in,
                              void* d_out, int out_size)
{
    const float* hs = (const float*)d_in[0];
    const float* Wq = (const float*)d_in[1];
    const float* bq = (const float*)d_in[2];
    const float* Wk = (const float*)d_in[3];
    const float* bk = (const float*)d_in[4];
    const float* Wv = (const float*)d_in[5];
    const float* bv = (const float*)d_in[6];
    const float* Wo = (const float*)d_in[7];
    const float* bo = (const float*)d_in[8];
    float* out = (float*)d_out;

    float *qd, *kd, *vd, *ctxd, *hstd, *wcd;
    cudaGetSymbolAddress((void**)&qd,   g_q);
    cudaGetSymbolAddress((void**)&kd,   g_k);
    cudaGetSymbolAddress((void**)&vd,   g_v);
    cudaGetSymbolAddress((void**)&ctxd, g_ctx);
    cudaGetSymbolAddress((void**)&hstd, g_hst);
    cudaGetSymbolAddress((void**)&wcd,  g_wc);
    float* wq_t = wcd + 0 * (size_t)DM_ * DM_;
    float* wk_t = wcd + 1 * (size_t)DM_ * DM_;
    float* wv_t = wcd + 2 * (size_t)DM_ * DM_;
    float* wo_t = wcd + 3 * (size_t)DM_ * DM_;

    const int gemm_smem = 3 * STAGEB;                       // 107520 B
    const int attn_smem = 3 * 64 * AST * (int)sizeof(unsigned);
    static int smem_set = 0;
    if (!smem_set) {
        cudaFuncSetAttribute(tc2_gemm,
                             cudaFuncAttributeMaxDynamicSharedMemorySize,
                             gemm_smem);
        cudaFuncSetAttribute(attn_mma_kernel,
                             cudaFuncAttributeMaxDynamicSharedMemorySize,
                             attn_smem);
        smem_set = 1;
    }

    rope_table_kernel<<<(S_ * (HD_ / 2) + 255) / 256, 256>>>();

    // Prepass: round inputs to tf32 so GEMMs can cp.async without cvt
    const int nh4 = BS_ * DM_ / 4, nw4 = DM_ * DM_ / 4;
    cvt_kernel<<<(nh4 + 255) / 256, 256>>>(hs, hstd, nh4);
    cvt_kernel<<<(nw4 + 255) / 256, 256>>>(Wq, wq_t, nw4);
    cvt_kernel<<<(nw4 + 255) / 256, 256>>>(Wk, wk_t, nw4);
    cvt_kernel<<<(nw4 + 255) / 256, 256>>>(Wv, wv_t, nw4);
    cvt_kernel<<<(nw4 + 255) / 256, 256>>>(Wo, wo_t, nw4);

    // Merged QKV: z=0 -> Q, z=1 -> K, z=2 -> V
    dim3 qkvgrid(GN / 128, 4096 / 128, 3);
    tc2_gemm<<<qkvgrid, 128, gemm_smem>>>(
        hstd, wq_t, wk_t, wv_t, bq, bk, bv, qd, kd, vd, -1);

    dim3 agrid(S_ / 64, B_ * NH_);
    attn_mma_kernel<<<agrid, 128, attn_smem>>>(qd, kd, vd, ctxd);

    dim3 ogrid(GN / 128, 4096 / 128, 1);
    tc2_gemm<<<ogrid, 128, gemm_smem>>>(
        ctxd, wo_t, nullptr, nullptr, bo, nullptr, nullptr, out, nullptr,
        nullptr, 2);
}

// round 7
// speedup vs baseline: 1.0161x; 1.0011x over previous
#include <cuda_runtime.h>
#include <cuda_bf16.h>
#include <math.h>
#include <stdint.h>

// Problem constants
#define B_  2
#define S_  2048
#define DM_ 2048
#define NH_ 16
#define HD_ 128
#define BS_ (B_ * S_)
#define SCALE_ 0.08838834764831845f   // 1/sqrt(128)
#define GK 2048
#define GN 2048

// ---------------------------------------------------------------------------
// Scratch
// ---------------------------------------------------------------------------
__device__ float g_q[B_ * NH_ * S_ * HD_];   // [bh][s][d] (pre-scaled)
__device__ float g_k[B_ * NH_ * S_ * HD_];
__device__ float g_v[B_ * NH_ * S_ * HD_];
__device__ float g_ctx[BS_ * DM_];           // tf32-rounded by attention
__device__ float g_hst[BS_ * DM_];           // tf32-rounded hidden states
__device__ float g_wc[4][DM_ * DM_];         // tf32-rounded Wq,Wk,Wv,Wo
__device__ float g_cos[S_ * (HD_ / 2)];
__device__ float g_sin[S_ * (HD_ / 2)];

// ---------------------------------------------------------------------------
// RoPE table (double precision)
// ---------------------------------------------------------------------------
__global__ void rope_table_kernel() {
    int idx = blockIdx.x * blockDim.x + threadIdx.x;
    if (idx >= S_ * (HD_ / 2)) return;
    int s = idx / (HD_ / 2);
    int i = idx % (HD_ / 2);
    double inv_freq = exp(-((double)(2 * i) / (double)HD_) * log(10000.0));
    double ang = (double)s * inv_freq;
    g_cos[idx] = (float)cos(ang);
    g_sin[idx] = (float)sin(ang);
}

__device__ __forceinline__ unsigned f2tf32(float x) {
    unsigned r;
    asm("cvt.rna.tf32.f32 %0, %1;" : "=r"(r) : "f"(x));
    return r;
}

// tf32-round prepass (float4 grid-stride)
__global__ void cvt_kernel(const float* __restrict__ in,
                           float* __restrict__ out, int n4) {
    int i = blockIdx.x * blockDim.x + threadIdx.x;
    if (i >= n4) return;
    float4 f = ((const float4*)in)[i];
    uint4 u;
    u.x = f2tf32(f.x); u.y = f2tf32(f.y);
    u.z = f2tf32(f.z); u.w = f2tf32(f.w);
    ((uint4*)out)[i] = u;
}

__device__ __forceinline__ uint32_t smem_u32(const void* p) {
    uint32_t a;
    asm("{ .reg .u64 t; cvta.to.shared.u64 t, %1; cvt.u32.u64 %0, t; }"
        : "=r"(a) : "l"(p));
    return a;
}

#define CP_ASYNC16(dst, src)                                                  \
    asm volatile("cp.async.cg.shared.global [%0], [%1], 16;"                  \
                 :: "r"(dst), "l"(src) : "memory")

#define MMA_TF32(Cc, a0, a1, a2, a3, b0, b1)                                  \
    asm volatile(                                                             \
        "mma.sync.aligned.m16n8k8.row.col.f32.tf32.tf32.f32 "                 \
        "{%0,%1,%2,%3}, {%4,%5,%6,%7}, {%8,%9}, {%0,%1,%2,%3};"               \
        : "+f"((Cc)[0]), "+f"((Cc)[1]), "+f"((Cc)[2]), "+f"((Cc)[3])          \
        : "r"(a0), "r"(a1), "r"(a2), "r"(a3), "r"(b0), "r"(b1))

// ---------------------------------------------------------------------------
// TF32 GEMM: 128x128 CTA tile, 128 threads (4 warps of 64x64), BK=32,
// cp.async 3-stage pipeline + register-level fragment double buffering
// (load->use distance 1 hides LDS latency inside each k-block).
// ---------------------------------------------------------------------------
#define NKB (GK / 32)
#define A_BYTES 18432                 // 128*36*4
#define STAGEB  35840                 // A_BYTES + 32*136*4

__global__ __launch_bounds__(128, 2) void tc2_gemm(
    const float* __restrict__ A,
    const float* __restrict__ W0, const float* __restrict__ W1,
    const float* __restrict__ W2,
    const float* __restrict__ b0p, const float* __restrict__ b1p,
    const float* __restrict__ b2p,
    float* __restrict__ C0, float* __restrict__ C1, float* __restrict__ C2,
    int mode0)
{
    extern __shared__ unsigned char smraw[];

    const float* W; const float* bias; float* C; int mode;
    if (mode0 >= 0) { W = W0; bias = b0p; C = C0; mode = mode0; }
    else {
        const int z = blockIdx.z;
        W    = (z == 0) ? W0 : (z == 1) ? W1 : W2;
        bias = (z == 0) ? b0p : (z == 1) ? b1p : b2p;
        C    = (z == 0) ? C0 : (z == 1) ? C1 : C2;
        mode = (z == 0) ? 0 : (z == 1) ? 3 : 1;
    }

    const int tid = threadIdx.x;
    const int lane = tid & 31, wid = tid >> 5;
    const int wm = wid >> 1, wn = wid & 1;
    const int gid = lane >> 2, tig = lane & 3;
    const int m0 = blockIdx.y * 128, n0 = blockIdx.x * 128;

    const uint32_t sb = smem_u32(smraw);

    const float* Asrc = A + (size_t)(m0 + tid) * GK;
    const int kr   = tid >> 2;
    const int nseg = (tid & 3) * 32;
    const float* Bsrc = W + (size_t)kr * GN + n0 + nseg;

    auto issue = [&](int ib) {
        const int p = ib % 3;
        const uint32_t ab = sb + p * STAGEB;
        const uint32_t bbs = ab + A_BYTES;
        const float* as = Asrc + ib * 32;
        #pragma unroll
        for (int j = 0; j < 8; j++)
            CP_ASYNC16(ab + tid * 144 + j * 16, as + j * 4);
        const float* bs = Bsrc + (size_t)(ib * 32) * GN;
        #pragma unroll
        for (int j = 0; j < 8; j++)
            CP_ASYNC16(bbs + kr * 544 + nseg * 4 + j * 16, bs + j * 4);
        asm volatile("cp.async.commit_group;" ::: "memory");
    };
    issue(0);
    issue(1);

    float acc[4][8][4];
    #pragma unroll
    for (int mi = 0; mi < 4; mi++)
        #pragma unroll
        for (int ni = 0; ni < 8; ni++)
            #pragma unroll
            for (int u = 0; u < 4; u++) acc[mi][ni][u] = 0.f;

    unsigned af[2][4][4], bf[2][8][2];

#define LOADF(bu, kk)                                                         \
    do {                                                                      \
        _Pragma("unroll")                                                     \
        for (int mi = 0; mi < 4; mi++) {                                      \
            const int mrow = wm * 64 + mi * 16 + gid;                         \
            af[bu][mi][0] = As[mrow * 36 + (kk) + tig];                       \
            af[bu][mi][1] = As[(mrow + 8) * 36 + (kk) + tig];                 \
            af[bu][mi][2] = As[mrow * 36 + (kk) + tig + 4];                   \
            af[bu][mi][3] = As[(mrow + 8) * 36 + (kk) + tig + 4];             \
        }                                                                     \
        _Pragma("unroll")                                                     \
        for (int ni = 0; ni < 8; ni++) {                                      \
            const int nc = wn * 64 + ni * 8 + gid;                            \
            bf[bu][ni][0] = Bs[((kk) + tig) * 136 + nc];                      \
            bf[bu][ni][1] = Bs[((kk) + tig + 4) * 136 + nc];                  \
        }                                                                     \
    } while (0)

#define MMAS(bu)                                                              \
    do {                                                                      \
        _Pragma("unroll")                                                     \
        for (int mi = 0; mi < 4; mi++)                                        \
            _Pragma("unroll")                                                 \
            for (int ni = 0; ni < 8; ni++)                                    \
                MMA_TF32(acc[mi][ni], af[bu][mi][0], af[bu][mi][1],           \
                         af[bu][mi][2], af[bu][mi][3],                        \
                         bf[bu][ni][0], bf[bu][ni][1]);                       \
    } while (0)

    for (int ib = 0; ib < NKB; ib++) {
        if (ib + 1 < NKB)
            asm volatile("cp.async.wait_group 1;" ::: "memory");
        else
            asm volatile("cp.async.wait_group 0;" ::: "memory");
        __syncthreads();
        if (ib + 2 < NKB) issue(ib + 2);

        const unsigned* As = (const unsigned*)(smraw + (ib % 3) * STAGEB);
        const unsigned* Bs = (const unsigned*)(smraw + (ib % 3) * STAGEB + A_BYTES);

        // register-level pipelined schedule: L0; {L1,M0}; {L2,M1}; {L3,M2}; M3
        LOADF(0, 0);
        LOADF(1, 8);  MMAS(0);
        LOADF(0, 16); MMAS(1);
        LOADF(1, 24); MMAS(0);
        MMAS(1);
    }

    // Epilogue: bias (+ RoPE) (+ scale) (+ scatter)
    #pragma unroll
    for (int ni = 0; ni < 8; ni++) {
        const int c = n0 + wn * 64 + ni * 8 + tig * 2;
        const float bv0 = bias[c], bv1 = bias[c + 1];
        #pragma unroll
        for (int mi = 0; mi < 4; mi++) {
            #pragma unroll
            for (int half = 0; half < 2; half++) {
                const int r = m0 + wm * 64 + mi * 16 + gid + half * 8;
                float v0 = acc[mi][ni][half * 2 + 0] + bv0;
                float v1 = acc[mi][ni][half * 2 + 1] + bv1;
                const int bb = r >> 11;
                const int s  = r & (S_ - 1);
                if (mode == 0 || mode == 3) {
                    const int pi = (c & (HD_ - 1)) >> 1;
                    const float cs = g_cos[s * (HD_ / 2) + pi];
                    const float sn = g_sin[s * (HD_ / 2) + pi];
                    const float e = v0, o = v1;
                    v0 = e * cs - o * sn;
                    v1 = o * cs + e * sn;
                    if (mode == 0) { v0 *= SCALE_; v1 *= SCALE_; }
                }
                float2 val; val.x = v0; val.y = v1;
                if (mode != 2) {
                    const int h = (c >> 7) & (NH_ - 1);
                    const int d = c & (HD_ - 1);
                    *(float2*)(C + (size_t)((bb * NH_ + h) * S_ + s) * HD_ + d) = val;
                } else {
                    *(float2*)(C + (size_t)r * GN + c) = val;
                }
            }
        }
    }
#undef LOADF
#undef MMAS
}

// ---------------------------------------------------------------------------
// Flash attention (causal) on tf32 mma.sync (R3-proven).
// ---------------------------------------------------------------------------
#define AST 132

__global__ __launch_bounds__(128) void attn_mma_kernel(
    const float* __restrict__ q, const float* __restrict__ k,
    const float* __restrict__ v, float* __restrict__ ctx)
{
    extern __shared__ unsigned smu[];
    unsigned* Qs = smu;
    unsigned* Ks = Qs + 64 * AST;
    unsigned* Vs = Ks + 64 * AST;

    const int tid  = threadIdx.x;
    const int lane = tid & 31, wid = tid >> 5;
    const int gid = lane >> 2, tig = lane & 3;
    const int bh = blockIdx.y;
    const int qt = gridDim.x - 1 - blockIdx.x;
    const int q0 = qt * 64;
    const int m0w = wid * 16;

    const float* qp = q + ((size_t)bh * S_ + q0) * HD_;
    const float* kb = k + (size_t)bh * S_ * HD_;
    const float* vb = v + (size_t)bh * S_ * HD_;

    for (int t = tid; t < 64 * 32; t += 128) {
        int r = t >> 5, c = (t & 31) * 4;
        float4 f = *(const float4*)&qp[r * HD_ + c];
        uint4 u;
        u.x = f2tf32(f.x); u.y = f2tf32(f.y);
        u.z = f2tf32(f.z); u.w = f2tf32(f.w);
        *(uint4*)&Qs[r * AST + c] = u;
    }

    float oacc[16][4];
    #pragma unroll
    for (int ni = 0; ni < 16; ni++)
        #pragma unroll
        for (int u = 0; u < 4; u++) oacc[ni][u] = 0.f;
    float mx0 = -1e30f, mx1 = -1e30f, ls0 = 0.f, ls1 = 0.f;

    const int nkv = qt + 1;
    for (int kt = 0; kt < nkv; kt++) {
        const int k0 = kt * 64;
        __syncthreads();
        const float* kp = kb + (size_t)k0 * HD_;
        const float* vp = vb + (size_t)k0 * HD_;
        for (int t = tid; t < 64 * 32; t += 128) {
            int r = t >> 5, c = (t & 31) * 4;
            float4 fk = *(const float4*)&kp[r * HD_ + c];
            float4 fv = *(const float4*)&vp[r * HD_ + c];
            uint4 uk, uv;
            uk.x = f2tf32(fk.x); uk.y = f2tf32(fk.y);
            uk.z = f2tf32(fk.z); uk.w = f2tf32(fk.w);
            uv.x = f2tf32(fv.x); uv.y = f2tf32(fv.y);
            uv.z = f2tf32(fv.z); uv.w = f2tf32(fv.w);
            *(uint4*)&Ks[r * AST + c] = uk;
            *(uint4*)&Vs[r * AST + c] = uv;
        }
        __syncthreads();

        float sacc[8][4];
        #pragma unroll
        for (int ni = 0; ni < 8; ni++)
            #pragma unroll
            for (int u = 0; u < 4; u++) sacc[ni][u] = 0.f;

        #pragma unroll
        for (int ks = 0; ks < 16; ks++) {
            const int kk = ks * 8;
            unsigned a0 = Qs[(m0w + gid) * AST + kk + tig];
            unsigned a1 = Qs[(m0w + gid + 8) * AST + kk + tig];
            unsigned a2 = Qs[(m0w + gid) * AST + kk + tig + 4];
            unsigned a3 = Qs[(m0w + gid + 8) * AST + kk + tig + 4];
            #pragma unroll
            for (int ni = 0; ni < 8; ni++) {
                unsigned b0 = Ks[(ni * 8 + gid) * AST + kk + tig];
                unsigned b1 = Ks[(ni * 8 + gid) * AST + kk + tig + 4];
                MMA_TF32(sacc[ni], a0, a1, a2, a3, b0, b1);
            }
        }

        if (kt == nkv - 1) {
            const int row0 = q0 + m0w + gid;
            #pragma unroll
            for (int ni = 0; ni < 8; ni++) {
                const int col = k0 + ni * 8 + tig * 2;
                if (col > row0)     sacc[ni][0] = -1e30f;
                if (col + 1 > row0) sacc[ni][1] = -1e30f;
                if (col > row0 + 8)     sacc[ni][2] = -1e30f;
                if (col + 1 > row0 + 8) sacc[ni][3] = -1e30f;
            }
        }

        float rm0 = -1e30f, rm1 = -1e30f;
        #pragma unroll
        for (int ni = 0; ni < 8; ni++) {
            rm0 = fmaxf(rm0, fmaxf(sacc[ni][0], sacc[ni][1]));
            rm1 = fmaxf(rm1, fmaxf(sacc[ni][2], sacc[ni][3]));
        }
        rm0 = fmaxf(rm0, __shfl_xor_sync(0xffffffffu, rm0, 1));
        rm0 = fmaxf(rm0, __shfl_xor_sync(0xffffffffu, rm0, 2));
        rm1 = fmaxf(rm1, __shfl_xor_sync(0xffffffffu, rm1, 1));
        rm1 = fmaxf(rm1, __shfl_xor_sync(0xffffffffu, rm1, 2));

        const float mn0 = fmaxf(mx0, rm0), mn1 = fmaxf(mx1, rm1);
        const float f0 = __expf(mx0 - mn0), f1 = __expf(mx1 - mn1);
        float rs0 = 0.f, rs1 = 0.f;
        #pragma unroll
        for (int ni = 0; ni < 8; ni++) {
            float p0 = __expf(sacc[ni][0] - mn0);
            float p1 = __expf(sacc[ni][1] - mn0);
            float p2 = __expf(sacc[ni][2] - mn1);
            float p3 = __expf(sacc[ni][3] - mn1);
            sacc[ni][0] = p0; sacc[ni][1] = p1;
            sacc[ni][2] = p2; sacc[ni][3] = p3;
            rs0 += p0 + p1; rs1 += p2 + p3;
        }
        rs0 += __shfl_xor_sync(0xffffffffu, rs0, 1);
        rs0 += __shfl_xor_sync(0xffffffffu, rs0, 2);
        rs1 += __shfl_xor_sync(0xffffffffu, rs1, 1);
        rs1 += __shfl_xor_sync(0xffffffffu, rs1, 2);
        ls0 = ls0 * f0 + rs0; ls1 = ls1 * f1 + rs1;
        mx0 = mn0; mx1 = mn1;

        #pragma unroll
        for (int ni = 0; ni < 16; ni++) {
            oacc[ni][0] *= f0; oacc[ni][1] *= f0;
            oacc[ni][2] *= f1; oacc[ni][3] *= f1;
        }

        #pragma unroll
        for (int kk = 0; kk < 8; kk++) {
            const int l1 = (gid << 2) | (tig >> 1);
            const int l2 = l1 + 2;
            float v00 = __shfl_sync(0xffffffffu, sacc[kk][0], l1);
            float v01 = __shfl_sync(0xffffffffu, sacc[kk][1], l1);
            float v10 = __shfl_sync(0xffffffffu, sacc[kk][2], l1);
            float v11 = __shfl_sync(0xffffffffu, sacc[kk][3], l1);
            float w00 = __shfl_sync(0xffffffffu, sacc[kk][0], l2);
            float w01 = __shfl_sync(0xffffffffu, sacc[kk][1], l2);
            float w10 = __shfl_sync(0xffffffffu, sacc[kk][2], l2);
            float w11 = __shfl_sync(0xffffffffu, sacc[kk][3], l2);
            const bool odd = tig & 1;
            unsigned pa0 = f2tf32(odd ? v01 : v00);
            unsigned pa1 = f2tf32(odd ? v11 : v10);
            unsigned pa2 = f2tf32(odd ? w01 : w00);
            unsigned pa3 = f2tf32(odd ? w11 : w10);
            #pragma unroll
            for (int ni = 0; ni < 16; ni++) {
                unsigned b0 = Vs[(kk * 8 + tig) * AST + ni * 8 + gid];
                unsigned b1 = Vs[(kk * 8 + tig + 4) * AST + ni * 8 + gid];
                MMA_TF32(oacc[ni], pa0, pa1, pa2, pa3, b0, b1);
            }
        }
    }

    const float inv0 = 1.f / ls0, inv1 = 1.f / ls1;
    const int b = bh >> 4, h = bh & 15;
    const int s0 = q0 + m0w + gid;
    #pragma unroll
    for (int ni = 0; ni < 16; ni++) {
        const int col = ni * 8 + tig * 2;
        float2 r0, r1;
        r0.x = __uint_as_float(f2tf32(oacc[ni][0] * inv0));
        r0.y = __uint_as_float(f2tf32(oacc[ni][1] * inv0));
        r1.x = __uint_as_float(f2tf32(oacc[ni][2] * inv1));
        r1.y = __uint_as_float(f2tf32(oacc[ni][3] * inv1));
        *(float2*)(ctx + (size_t)(b * S_ + s0) * DM_ + h * HD_ + col) = r0;
        *(float2*)(ctx + (size_t)(b * S_ + s0 + 8) * DM_ + h * HD_ + col) = r1;
    }
}

// ---------------------------------------------------------------------------
// Launch
// ---------------------------------------------------------------------------
extern "C" void kernel_launch(void* const* d_in, const int* in_sizes, int n_in,
                              void* d_out, int out_size)
{
    const float* hs = (const float*)d_in[0];
    const float* Wq = (const float*)d_in[1];
    const float* bq = (const float*)d_in[2];
    const float* Wk = (const float*)d_in[3];
    const float* bk = (const float*)d_in[4];
    const float* Wv = (const float*)d_in[5];
    const float* bv = (const float*)d_in[6];
    const float* Wo = (const float*)d_in[7];
    const float* bo = (const float*)d_in[8];
    float* out = (float*)d_out;

    float *qd, *kd, *vd, *ctxd, *hstd, *wcd;
    cudaGetSymbolAddress((void**)&qd,   g_q);
    cudaGetSymbolAddress((void**)&kd,   g_k);
    cudaGetSymbolAddress((void**)&vd,   g_v);
    cudaGetSymbolAddress((void**)&ctxd, g_ctx);
    cudaGetSymbolAddress((void**)&hstd, g_hst);
    cudaGetSymbolAddress((void**)&wcd,  g_wc);
    float* wq_t = wcd + 0 * (size_t)DM_ * DM_;
    float* wk_t = wcd + 1 * (size_t)DM_ * DM_;
    float* wv_t = wcd + 2 * (size_t)DM_ * DM_;
    float* wo_t = wcd + 3 * (size_t)DM_ * DM_;

    const int gemm_smem = 3 * STAGEB;
    const int attn_smem = 3 * 64 * AST * (int)sizeof(unsigned);
    static int smem_set = 0;
    if (!smem_set) {
        cudaFuncSetAttribute(tc2_gemm,
                             cudaFuncAttributeMaxDynamicSharedMemorySize,
                             gemm_smem);
        cudaFuncSetAttribute(attn_mma_kernel,
                             cudaFuncAttributeMaxDynamicSharedMemorySize,
                             attn_smem);
        smem_set = 1;
    }

    rope_table_kernel<<<(S_ * (HD_ / 2) + 255) / 256, 256>>>();

    const int nh4 = BS_ * DM_ / 4, nw4 = DM_ * DM_ / 4;
    cvt_kernel<<<(nh4 + 255) / 256, 256>>>(hs, hstd, nh4);
    cvt_kernel<<<(nw4 + 255) / 256, 256>>>(Wq, wq_t, nw4);
    cvt_kernel<<<(nw4 + 255) / 256, 256>>>(Wk, wk_t, nw4);
    cvt_kernel<<<(nw4 + 255) / 256, 256>>>(Wv, wv_t, nw4);
    cvt_kernel<<<(nw4 + 255) / 256, 256>>>(Wo, wo_t, nw4);

    dim3 qkvgrid(GN / 128, 4096 / 128, 3);
    tc2_gemm<<<qkvgrid, 128, gemm_smem>>>(
        hstd, wq_t, wk_t, wv_t, bq, bk, bv, qd, kd, vd, -1);

    dim3 agrid(S_ / 64, B_ * NH_);
    attn_mma_kernel<<<agrid, 128, attn_smem>>>(qd, kd, vd, ctxd);

    dim3 ogrid(GN / 128, 4096 / 128, 1);
    tc2_gemm<<<ogrid, 128, gemm_smem>>>(
        ctxd, wo_t, nullptr, nullptr, bo, nullptr, nullptr, out, nullptr,
        nullptr, 2);
}

// round 8
// speedup vs baseline: 1.6232x; 1.5974x over previous
#include <cuda_runtime.h>
#include <cuda_fp16.h>
#include <math.h>
#include <stdint.h>

// Problem constants
#define B_  2
#define S_  2048
#define DM_ 2048
#define NH_ 16
#define HD_ 128
#define BS_ (B_ * S_)
#define SCALE_ 0.08838834764831845f   // 1/sqrt(128)
#define GK 2048
#define GN 2048

// ---------------------------------------------------------------------------
// Scratch
// ---------------------------------------------------------------------------
__device__ float g_q[B_ * NH_ * S_ * HD_];   // [bh][s][d] (pre-scaled)
__device__ float g_k[B_ * NH_ * S_ * HD_];
__device__ float g_v[B_ * NH_ * S_ * HD_];
__device__ float g_ctx[BS_ * DM_];
__device__ float g_cos[S_ * (HD_ / 2)];
__device__ float g_sin[S_ * (HD_ / 2)];

// ---------------------------------------------------------------------------
// RoPE table (double precision)
// ---------------------------------------------------------------------------
__global__ void rope_table_kernel() {
    int idx = blockIdx.x * blockDim.x + threadIdx.x;
    if (idx >= S_ * (HD_ / 2)) return;
    int s = idx / (HD_ / 2);
    int i = idx % (HD_ / 2);
    double inv_freq = exp(-((double)(2 * i) / (double)HD_) * log(10000.0));
    double ang = (double)s * inv_freq;
    g_cos[idx] = (float)cos(ang);
    g_sin[idx] = (float)sin(ang);
}

__device__ __forceinline__ unsigned h2u(float lo, float hi) {
    __half2 h = __floats2half2_rn(lo, hi);
    return *(unsigned*)&h;
}

#define MMA_F16(Cc, a0, a1, a2, a3, b0, b1)                                   \
    asm volatile(                                                             \
        "mma.sync.aligned.m16n8k16.row.col.f32.f16.f16.f32 "                  \
        "{%0,%1,%2,%3}, {%4,%5,%6,%7}, {%8,%9}, {%0,%1,%2,%3};"               \
        : "+f"((Cc)[0]), "+f"((Cc)[1]), "+f"((Cc)[2]), "+f"((Cc)[3])          \
        : "r"(a0), "r"(a1), "r"(a2), "r"(a3), "r"(b0), "r"(b1))

// ---------------------------------------------------------------------------
// FP16 GEMM: C[4096,2048] = A[4096,2048] @ W[2048,2048] + bias
// 128x128 CTA tile, BK=32, 256 threads, 8 warps of 64x32, m16n8k16.
// As2: [m][k/2] half2, row stride 20 words (16 used) -> conflict-free frags.
// Bs2: [k/2][n] half2 (pairs along k), row stride 136 words -> conflict-free.
// mode 0: rope+scale+scatter (Q)  mode 3: rope+scatter (K)
// mode 1: scatter (V)             mode 2: row-major write (O proj)
// ---------------------------------------------------------------------------
#define ASTRIDE 20
#define BSTRIDE 136

__global__ __launch_bounds__(256) void hgemm_kernel(
    const float* __restrict__ A, const float* __restrict__ W,
    const float* __restrict__ bias, float* __restrict__ C, int mode)
{
    __shared__ unsigned As2[128 * ASTRIDE];   // 10240 B
    __shared__ unsigned Bs2[16 * BSTRIDE];    // 8704 B

    const int tid  = threadIdx.x;
    const int lane = tid & 31, wid = tid >> 5;
    const int warpM = wid >> 2, warpN = wid & 3;     // 2 x 4
    const int gid = lane >> 2, tig = lane & 3;
    const int m0 = blockIdx.y * 128, n0 = blockIdx.x * 128;

    // staging assignments
    const int arow = tid >> 1;            // 0..127
    const int ak   = (tid & 1) * 16;      // k offset 0/16
    const int bkp  = tid >> 4;            // 0..15 k-pair row
    const int bns  = (tid & 15) * 8;      // n offset

    const float* Ap  = A + (size_t)(m0 + arow) * GK + ak;
    const float* Wp0 = W + (size_t)(2 * bkp) * GN + n0 + bns;
    const float* Wp1 = Wp0 + GN;

    float acc[4][4][4];
    #pragma unroll
    for (int mi = 0; mi < 4; mi++)
        #pragma unroll
        for (int ni = 0; ni < 4; ni++)
            #pragma unroll
            for (int u = 0; u < 4; u++) acc[mi][ni][u] = 0.f;

    float4 ra[4], rb[4];
    #pragma unroll
    for (int j = 0; j < 4; j++) ra[j] = *(const float4*)(Ap + j * 4);
    rb[0] = *(const float4*)(Wp0);
    rb[1] = *(const float4*)(Wp0 + 4);
    rb[2] = *(const float4*)(Wp1);
    rb[3] = *(const float4*)(Wp1 + 4);

    for (int kb = 0; kb < GK; kb += 32) {
        // stage A (pairs along k)
        {
            uint4 u0, u1;
            u0.x = h2u(ra[0].x, ra[0].y); u0.y = h2u(ra[0].z, ra[0].w);
            u0.z = h2u(ra[1].x, ra[1].y); u0.w = h2u(ra[1].z, ra[1].w);
            u1.x = h2u(ra[2].x, ra[2].y); u1.y = h2u(ra[2].z, ra[2].w);
            u1.z = h2u(ra[3].x, ra[3].y); u1.w = h2u(ra[3].z, ra[3].w);
            *(uint4*)&As2[arow * ASTRIDE + ak / 2]     = u0;
            *(uint4*)&As2[arow * ASTRIDE + ak / 2 + 4] = u1;
        }
        // stage B (interleave rows 2kp, 2kp+1 -> half2 pairs along k)
        {
            uint4 u0, u1;
            u0.x = h2u(rb[0].x, rb[2].x); u0.y = h2u(rb[0].y, rb[2].y);
            u0.z = h2u(rb[0].z, rb[2].z); u0.w = h2u(rb[0].w, rb[2].w);
            u1.x = h2u(rb[1].x, rb[3].x); u1.y = h2u(rb[1].y, rb[3].y);
            u1.z = h2u(rb[1].z, rb[3].z); u1.w = h2u(rb[1].w, rb[3].w);
            *(uint4*)&Bs2[bkp * BSTRIDE + bns]     = u0;
            *(uint4*)&Bs2[bkp * BSTRIDE + bns + 4] = u1;
        }
        __syncthreads();

        // prefetch next k-block (overlaps compute)
        if (kb + 32 < GK) {
            #pragma unroll
            for (int j = 0; j < 4; j++)
                ra[j] = *(const float4*)(Ap + kb + 32 + j * 4);
            rb[0] = *(const float4*)(Wp0 + (size_t)(kb + 32) * GN);
            rb[1] = *(const float4*)(Wp0 + (size_t)(kb + 32) * GN + 4);
            rb[2] = *(const float4*)(Wp1 + (size_t)(kb + 32) * GN);
            rb[3] = *(const float4*)(Wp1 + (size_t)(kb + 32) * GN + 4);
        }

        #pragma unroll
        for (int kk2 = 0; kk2 < 16; kk2 += 8) {    // two k16 steps
            unsigned af[4][4], bf[4][2];
            #pragma unroll
            for (int mi = 0; mi < 4; mi++) {
                const int mr = warpM * 64 + mi * 16 + gid;
                af[mi][0] = As2[mr * ASTRIDE + kk2 + tig];
                af[mi][1] = As2[(mr + 8) * ASTRIDE + kk2 + tig];
                af[mi][2] = As2[mr * ASTRIDE + kk2 + tig + 4];
                af[mi][3] = As2[(mr + 8) * ASTRIDE + kk2 + tig + 4];
            }
            #pragma unroll
            for (int ni = 0; ni < 4; ni++) {
                const int nc = warpN * 32 + ni * 8 + gid;
                bf[ni][0] = Bs2[(kk2 + tig) * BSTRIDE + nc];
                bf[ni][1] = Bs2[(kk2 + tig + 4) * BSTRIDE + nc];
            }
            #pragma unroll
            for (int mi = 0; mi < 4; mi++)
                #pragma unroll
                for (int ni = 0; ni < 4; ni++)
                    MMA_F16(acc[mi][ni], af[mi][0], af[mi][1], af[mi][2],
                            af[mi][3], bf[ni][0], bf[ni][1]);
        }
        __syncthreads();
    }

    // Epilogue: bias (+ RoPE) (+ scale) (+ scatter)
    #pragma unroll
    for (int ni = 0; ni < 4; ni++) {
        const int c = n0 + warpN * 32 + ni * 8 + tig * 2;
        const float bv0 = bias[c], bv1 = bias[c + 1];
        #pragma unroll
        for (int mi = 0; mi < 4; mi++) {
            #pragma unroll
            for (int half = 0; half < 2; half++) {
                const int r = m0 + warpM * 64 + mi * 16 + gid + half * 8;
                float v0 = acc[mi][ni][half * 2 + 0] + bv0;
                float v1 = acc[mi][ni][half * 2 + 1] + bv1;
                const int bb = r >> 11;
                const int s  = r & (S_ - 1);
                if (mode == 0 || mode == 3) {
                    const int pi = (c & (HD_ - 1)) >> 1;
                    const float cs = g_cos[s * (HD_ / 2) + pi];
                    const float sn = g_sin[s * (HD_ / 2) + pi];
                    const float e = v0, o = v1;
                    v0 = e * cs - o * sn;
                    v1 = o * cs + e * sn;
                    if (mode == 0) { v0 *= SCALE_; v1 *= SCALE_; }
                }
                float2 val; val.x = v0; val.y = v1;
                if (mode != 2) {
                    const int h = (c >> 7) & (NH_ - 1);
                    const int d = c & (HD_ - 1);
                    *(float2*)(C + (size_t)((bb * NH_ + h) * S_ + s) * HD_ + d) = val;
                } else {
                    *(float2*)(C + (size_t)r * GN + c) = val;
                }
            }
        }
    }
}

// ---------------------------------------------------------------------------
// Flash attention (causal), fp16 m16n8k16 tensor cores.
// CTA: 64 q-rows, 4 warps x 16 rows. KV tiles of 64. HD=128.
// Qs2/Ks2: [row][d/2] half2, stride 68 words. Vs2: [s/2][d] half2 pairs
// along s, stride 136 words. P->A-frag needs NO shuffles (layout identity).
// ---------------------------------------------------------------------------
#define QST 68     // Q/K row stride in words (64 used)
#define VST 136    // V row stride in words (128 used)
#define QWORDS (64 * QST)

__global__ __launch_bounds__(128) void attn_h_kernel(
    const float* __restrict__ q, const float* __restrict__ k,
    const float* __restrict__ v, float* __restrict__ ctx)
{
    extern __shared__ unsigned smu[];
    unsigned* Qs2 = smu;                  // 64*68
    unsigned* Ks2 = Qs2 + QWORDS;         // 64*68
    unsigned* Vs2 = Ks2 + QWORDS;         // 32*136 = 4352 words

    const int tid  = threadIdx.x;
    const int lane = tid & 31, wid = tid >> 5;
    const int gid = lane >> 2, tig = lane & 3;
    const int bh = blockIdx.y;
    const int qt = gridDim.x - 1 - blockIdx.x;   // heavy tiles first
    const int q0 = qt * 64;
    const int m0w = wid * 16;

    const float* qp = q + ((size_t)bh * S_ + q0) * HD_;
    const float* kb = k + (size_t)bh * S_ * HD_;
    const float* vb = v + (size_t)bh * S_ * HD_;

    // Load Q tile: float4 -> 2 half2 (pairs along d)
    for (int t = tid; t < 64 * 32; t += 128) {
        int r = t >> 5, c = (t & 31) * 4;
        float4 f = *(const float4*)&qp[r * HD_ + c];
        uint2 u;
        u.x = h2u(f.x, f.y); u.y = h2u(f.z, f.w);
        *(uint2*)&Qs2[r * QST + c / 2] = u;
    }

    float oacc[16][4];
    #pragma unroll
    for (int ni = 0; ni < 16; ni++)
        #pragma unroll
        for (int u = 0; u < 4; u++) oacc[ni][u] = 0.f;
    float mx0 = -1e30f, mx1 = -1e30f, ls0 = 0.f, ls1 = 0.f;

    const int nkv = qt + 1;
    for (int kt = 0; kt < nkv; kt++) {
        const int k0 = kt * 64;
        __syncthreads();
        const float* kp = kb + (size_t)k0 * HD_;
        const float* vp = vb + (size_t)k0 * HD_;
        // K: pairs along d
        for (int t = tid; t < 64 * 32; t += 128) {
            int r = t >> 5, c = (t & 31) * 4;
            float4 f = *(const float4*)&kp[r * HD_ + c];
            uint2 u;
            u.x = h2u(f.x, f.y); u.y = h2u(f.z, f.w);
            *(uint2*)&Ks2[r * QST + c / 2] = u;
        }
        // V: pairs along s (interleave rows 2s2, 2s2+1)
        for (int t = tid; t < 32 * 32; t += 128) {
            int s2 = t >> 5, c = (t & 31) * 4;
            float4 f0 = *(const float4*)&vp[(2 * s2) * HD_ + c];
            float4 f1 = *(const float4*)&vp[(2 * s2 + 1) * HD_ + c];
            uint4 u;
            u.x = h2u(f0.x, f1.x); u.y = h2u(f0.y, f1.y);
            u.z = h2u(f0.z, f1.z); u.w = h2u(f0.w, f1.w);
            *(uint4*)&Vs2[s2 * VST + c] = u;
        }
        __syncthreads();

        // ---- S = Q @ K^T (16x64 per warp), 8 k16 steps over d ----
        float sacc[8][4];
        #pragma unroll
        for (int ni = 0; ni < 8; ni++)
            #pragma unroll
            for (int u = 0; u < 4; u++) sacc[ni][u] = 0.f;

        #pragma unroll
        for (int ks = 0; ks < 8; ks++) {
            const int kw = ks * 8;   // half2 offset in row
            unsigned a0 = Qs2[(m0w + gid) * QST + kw + tig];
            unsigned a1 = Qs2[(m0w + gid + 8) * QST + kw + tig];
            unsigned a2 = Qs2[(m0w + gid) * QST + kw + tig + 4];
            unsigned a3 = Qs2[(m0w + gid + 8) * QST + kw + tig + 4];
            #pragma unroll
            for (int ni = 0; ni < 8; ni++) {
                unsigned b0 = Ks2[(ni * 8 + gid) * QST + kw + tig];
                unsigned b1 = Ks2[(ni * 8 + gid) * QST + kw + tig + 4];
                MMA_F16(sacc[ni], a0, a1, a2, a3, b0, b1);
            }
        }

        // ---- causal mask (diagonal tile only) ----
        if (kt == nkv - 1) {
            const int row0 = q0 + m0w + gid;
            #pragma unroll
            for (int ni = 0; ni < 8; ni++) {
                const int col = k0 + ni * 8 + tig * 2;
                if (col > row0)     sacc[ni][0] = -1e30f;
                if (col + 1 > row0) sacc[ni][1] = -1e30f;
                if (col > row0 + 8)     sacc[ni][2] = -1e30f;
                if (col + 1 > row0 + 8) sacc[ni][3] = -1e30f;
            }
        }

        // ---- online softmax ----
        float rm0 = -1e30f, rm1 = -1e30f;
        #pragma unroll
        for (int ni = 0; ni < 8; ni++) {
            rm0 = fmaxf(rm0, fmaxf(sacc[ni][0], sacc[ni][1]));
            rm1 = fmaxf(rm1, fmaxf(sacc[ni][2], sacc[ni][3]));
        }
        rm0 = fmaxf(rm0, __shfl_xor_sync(0xffffffffu, rm0, 1));
        rm0 = fmaxf(rm0, __shfl_xor_sync(0xffffffffu, rm0, 2));
        rm1 = fmaxf(rm1, __shfl_xor_sync(0xffffffffu, rm1, 1));
        rm1 = fmaxf(rm1, __shfl_xor_sync(0xffffffffu, rm1, 2));

        const float mn0 = fmaxf(mx0, rm0), mn1 = fmaxf(mx1, rm1);
        const float f0 = __expf(mx0 - mn0), f1 = __expf(mx1 - mn1);
        float rs0 = 0.f, rs1 = 0.f;
        #pragma unroll
        for (int ni = 0; ni < 8; ni++) {
            float p0 = __expf(sacc[ni][0] - mn0);
            float p1 = __expf(sacc[ni][1] - mn0);
            float p2 = __expf(sacc[ni][2] - mn1);
            float p3 = __expf(sacc[ni][3] - mn1);
            sacc[ni][0] = p0; sacc[ni][1] = p1;
            sacc[ni][2] = p2; sacc[ni][3] = p3;
            rs0 += p0 + p1; rs1 += p2 + p3;
        }
        rs0 += __shfl_xor_sync(0xffffffffu, rs0, 1);
        rs0 += __shfl_xor_sync(0xffffffffu, rs0, 2);
        rs1 += __shfl_xor_sync(0xffffffffu, rs1, 1);
        rs1 += __shfl_xor_sync(0xffffffffu, rs1, 2);
        ls0 = ls0 * f0 + rs0; ls1 = ls1 * f1 + rs1;
        mx0 = mn0; mx1 = mn1;

        #pragma unroll
        for (int ni = 0; ni < 16; ni++) {
            oacc[ni][0] *= f0; oacc[ni][1] *= f0;
            oacc[ni][2] *= f1; oacc[ni][3] *= f1;
        }

        // ---- O += P @ V : P A-frags come straight from sacc (no shuffles)
        #pragma unroll
        for (int j = 0; j < 4; j++) {         // k16 steps over s (64 = 4*16)
            unsigned pa0 = h2u(sacc[2 * j][0], sacc[2 * j][1]);
            unsigned pa1 = h2u(sacc[2 * j][2], sacc[2 * j][3]);
            unsigned pa2 = h2u(sacc[2 * j + 1][0], sacc[2 * j + 1][1]);
            unsigned pa3 = h2u(sacc[2 * j + 1][2], sacc[2 * j + 1][3]);
            #pragma unroll
            for (int ni = 0; ni < 16; ni++) {
                const int nc = ni * 8 + gid;
                unsigned b0 = Vs2[(8 * j + tig) * VST + nc];
                unsigned b1 = Vs2[(8 * j + 4 + tig) * VST + nc];
                MMA_F16(oacc[ni], pa0, pa1, pa2, pa3, b0, b1);
            }
        }
    }

    // ---- normalize + write ctx ----
    const float inv0 = 1.f / ls0, inv1 = 1.f / ls1;
    const int b = bh >> 4, h = bh & 15;
    const int s0 = q0 + m0w + gid;
    #pragma unroll
    for (int ni = 0; ni < 16; ni++) {
        const int col = ni * 8 + tig * 2;
        float2 r0; r0.x = oacc[ni][0] * inv0; r0.y = oacc[ni][1] * inv0;
        float2 r1; r1.x = oacc[ni][2] * inv1; r1.y = oacc[ni][3] * inv1;
        *(float2*)(ctx + (size_t)(b * S_ + s0) * DM_ + h * HD_ + col) = r0;
        *(float2*)(ctx + (size_t)(b * S_ + s0 + 8) * DM_ + h * HD_ + col) = r1;
    }
}

// ---------------------------------------------------------------------------
// Launch
// ---------------------------------------------------------------------------
extern "C" void kernel_launch(void* const* d_in, const int* in_sizes, int n_in,
                              void* d_out, int out_size)
{
    const float* hs = (const float*)d_in[0];
    const float* Wq = (const float*)d_in[1];
    const float* bq = (const float*)d_in[2];
    const float* Wk = (const float*)d_in[3];
    const float* bk = (const float*)d_in[4];
    const float* Wv = (const float*)d_in[5];
    const float* bv = (const float*)d_in[6];
    const float* Wo = (const float*)d_in[7];
    const float* bo = (const float*)d_in[8];
    float* out = (float*)d_out;

    float *qd, *kd, *vd, *ctxd;
    cudaGetSymbolAddress((void**)&qd,   g_q);
    cudaGetSymbolAddress((void**)&kd,   g_k);
    cudaGetSymbolAddress((void**)&vd,   g_v);
    cudaGetSymbolAddress((void**)&ctxd, g_ctx);

    const int attn_smem = (2 * QWORDS + 32 * VST) * (int)sizeof(unsigned); // 52224
    static int smem_set = 0;
    if (!smem_set) {
        cudaFuncSetAttribute(attn_h_kernel,
                             cudaFuncAttributeMaxDynamicSharedMemorySize,
                             attn_smem);
        smem_set = 1;
    }

    rope_table_kernel<<<(S_ * (HD_ / 2) + 255) / 256, 256>>>();

    dim3 ggrid(GN / 128, 4096 / 128);
    hgemm_kernel<<<ggrid, 256>>>(hs, Wq, bq, qd, 0);   // Q: rope + scale
    hgemm_kernel<<<ggrid, 256>>>(hs, Wk, bk, kd, 3);   // K: rope
    hgemm_kernel<<<ggrid, 256>>>(hs, Wv, bv, vd, 1);   // V

    dim3 agrid(S_ / 64, B_ * NH_);
    attn_h_kernel<<<agrid, 128, attn_smem>>>(qd, kd, vd, ctxd);

    hgemm_kernel<<<ggrid, 256>>>(ctxd, Wo, bo, out, 2);
}

// round 9
// speedup vs baseline: 2.4949x; 1.5370x over previous
#include <cuda_runtime.h>
#include <cuda_fp16.h>
#include <math.h>
#include <stdint.h>

// Problem constants
#define B_  2
#define S_  2048
#define DM_ 2048
#define NH_ 16
#define HD_ 128
#define BS_ (B_ * S_)
#define SCALE_ 0.08838834764831845f   // 1/sqrt(128)
#define GK 2048
#define GN 2048

// ---------------------------------------------------------------------------
// Scratch
// ---------------------------------------------------------------------------
__device__ __half g_qh[B_ * NH_ * S_ * HD_];   // [bh][s][d] (pre-scaled)
__device__ __half g_kh[B_ * NH_ * S_ * HD_];
__device__ __half g_vh[B_ * NH_ * S_ * HD_];
__device__ __half g_ctxh[BS_ * DM_];
__device__ __half g_ah[BS_ * DM_];             // half hidden states
__device__ unsigned g_wt[4][(DM_ / 2) * DM_];  // k-pair-interleaved half2 W
__device__ float g_cos[S_ * (HD_ / 2)];
__device__ float g_sin[S_ * (HD_ / 2)];

// ---------------------------------------------------------------------------
// RoPE table (double precision)
// ---------------------------------------------------------------------------
__global__ void rope_table_kernel() {
    int idx = blockIdx.x * blockDim.x + threadIdx.x;
    if (idx >= S_ * (HD_ / 2)) return;
    int s = idx / (HD_ / 2);
    int i = idx % (HD_ / 2);
    double inv_freq = exp(-((double)(2 * i) / (double)HD_) * log(10000.0));
    double ang = (double)s * inv_freq;
    g_cos[idx] = (float)cos(ang);
    g_sin[idx] = (float)sin(ang);
}

__device__ __forceinline__ unsigned h2u(float lo, float hi) {
    __half2 h = __floats2half2_rn(lo, hi);
    return *(unsigned*)&h;
}

// hs f32 -> half (8 elems/thread)
__global__ void cvt_a_kernel(const float* __restrict__ in,
                             __half* __restrict__ out, int n8) {
    int i = blockIdx.x * blockDim.x + threadIdx.x;
    if (i >= n8) return;
    float4 f0 = ((const float4*)in)[2 * i];
    float4 f1 = ((const float4*)in)[2 * i + 1];
    uint4 u;
    u.x = h2u(f0.x, f0.y); u.y = h2u(f0.z, f0.w);
    u.z = h2u(f1.x, f1.y); u.w = h2u(f1.z, f1.w);
    ((uint4*)out)[i] = u;
}

// W[k][n] f32 -> Wt[k2][n] = half2(W[2k2][n], W[2k2+1][n])  (4 n per thread)
__global__ void cvt_w_kernel(const float* __restrict__ W,
                             unsigned* __restrict__ Wt) {
    int idx = blockIdx.x * blockDim.x + threadIdx.x;
    if (idx >= (GK / 2) * (GN / 4)) return;
    int k2 = idx / (GN / 4);
    int n  = (idx % (GN / 4)) * 4;
    float4 f0 = *(const float4*)(W + (size_t)(2 * k2) * GN + n);
    float4 f1 = *(const float4*)(W + (size_t)(2 * k2 + 1) * GN + n);
    uint4 u;
    u.x = h2u(f0.x, f1.x); u.y = h2u(f0.y, f1.y);
    u.z = h2u(f0.z, f1.z); u.w = h2u(f0.w, f1.w);
    *(uint4*)(Wt + (size_t)k2 * GN + n) = u;
}

__device__ __forceinline__ uint32_t smem_u32(const void* p) {
    uint32_t a;
    asm("{ .reg .u64 t; cvta.to.shared.u64 t, %1; cvt.u32.u64 %0, t; }"
        : "=r"(a) : "l"(p));
    return a;
}

#define CP_ASYNC16(dst, src)                                                  \
    asm volatile("cp.async.cg.shared.global [%0], [%1], 16;"                  \
                 :: "r"(dst), "l"(src) : "memory")

#define MMA_F16(Cc, a0, a1, a2, a3, b0, b1)                                   \
    asm volatile(                                                             \
        "mma.sync.aligned.m16n8k16.row.col.f32.f16.f16.f32 "                  \
        "{%0,%1,%2,%3}, {%4,%5,%6,%7}, {%8,%9}, {%0,%1,%2,%3};"               \
        : "+f"((Cc)[0]), "+f"((Cc)[1]), "+f"((Cc)[2]), "+f"((Cc)[3])          \
        : "r"(a0), "r"(a1), "r"(a2), "r"(a3), "r"(b0), "r"(b1))

// ---------------------------------------------------------------------------
// FP16 GEMM with cp.async: C[4096,2048] = A @ W + bias.
// 128x128 CTA, 256 thr, 8 warps of 64x32, m16n8k16, 3-stage pipeline.
// As2: [m][k/2] stride 20 words; Bs2: [k2][n] stride 136 words (R8 layouts).
// mode 0: rope+scale -> half scatter (Q)  mode 3: rope -> half scatter (K)
// mode 1: half scatter (V)                mode 2: float row-major (O proj)
// mode0 < 0: derive from blockIdx.z (merged QKV).
// ---------------------------------------------------------------------------
#define ASTRIDE 20
#define BSTRIDE 136
#define ABYTES  (128 * ASTRIDE * 4)    // 10240
#define STAGEB  (ABYTES + 16 * BSTRIDE * 4)   // 18944
#define NKB (GK / 32)

__global__ __launch_bounds__(256) void hgemm2_kernel(
    const __half* __restrict__ Ah,
    const unsigned* __restrict__ Wt0, const unsigned* __restrict__ Wt1,
    const unsigned* __restrict__ Wt2,
    const float* __restrict__ b0p, const float* __restrict__ b1p,
    const float* __restrict__ b2p,
    void* __restrict__ C0, void* __restrict__ C1, void* __restrict__ C2,
    int mode0)
{
    extern __shared__ unsigned char smraw[];

    const unsigned* Wt; const float* bias; void* C; int mode;
    if (mode0 >= 0) { Wt = Wt0; bias = b0p; C = C0; mode = mode0; }
    else {
        const int z = blockIdx.z;
        Wt   = (z == 0) ? Wt0 : (z == 1) ? Wt1 : Wt2;
        bias = (z == 0) ? b0p : (z == 1) ? b1p : b2p;
        C    = (z == 0) ? C0 : (z == 1) ? C1 : C2;
        mode = (z == 0) ? 0 : (z == 1) ? 3 : 1;
    }

    const int tid  = threadIdx.x;
    const int lane = tid & 31, wid = tid >> 5;
    const int warpM = wid >> 2, warpN = wid & 3;
    const int gid = lane >> 2, tig = lane & 3;
    const int m0 = blockIdx.y * 128, n0 = blockIdx.x * 128;

    const uint32_t sb = smem_u32(smraw);

    const int arow = tid >> 1, ac = tid & 1;
    const __half* asrc0 = Ah + (size_t)(m0 + arow) * GK + ac * 16;
    const int brow = tid >> 4, bc = tid & 15;
    const unsigned* bsrc0 = Wt + (size_t)brow * GN + n0 + bc * 8;

    auto issue = [&](int ib) {
        const uint32_t base = sb + (ib % 3) * STAGEB;
        const __half* as = asrc0 + ib * 32;
        CP_ASYNC16(base + arow * 80 + ac * 32, as);
        CP_ASYNC16(base + arow * 80 + ac * 32 + 16, as + 8);
        const unsigned* bs = bsrc0 + (size_t)(ib * 16) * GN;
        CP_ASYNC16(base + ABYTES + brow * 544 + bc * 32, bs);
        CP_ASYNC16(base + ABYTES + brow * 544 + bc * 32 + 16, bs + 4);
        asm volatile("cp.async.commit_group;" ::: "memory");
    };
    issue(0);
    issue(1);

    float acc[4][4][4];
    #pragma unroll
    for (int mi = 0; mi < 4; mi++)
        #pragma unroll
        for (int ni = 0; ni < 4; ni++)
            #pragma unroll
            for (int u = 0; u < 4; u++) acc[mi][ni][u] = 0.f;

    for (int ib = 0; ib < NKB; ib++) {
        if (ib + 2 < NKB)
            asm volatile("cp.async.wait_group 1;" ::: "memory");
        else
            asm volatile("cp.async.wait_group 0;" ::: "memory");
        __syncthreads();
        if (ib + 2 < NKB) issue(ib + 2);

        const unsigned* As2 = (const unsigned*)(smraw + (ib % 3) * STAGEB);
        const unsigned* Bs2 = (const unsigned*)(smraw + (ib % 3) * STAGEB + ABYTES);

        #pragma unroll
        for (int kk2 = 0; kk2 < 16; kk2 += 8) {
            unsigned af[4][4], bf[4][2];
            #pragma unroll
            for (int mi = 0; mi < 4; mi++) {
                const int mr = warpM * 64 + mi * 16 + gid;
                af[mi][0] = As2[mr * ASTRIDE + kk2 + tig];
                af[mi][1] = As2[(mr + 8) * ASTRIDE + kk2 + tig];
                af[mi][2] = As2[mr * ASTRIDE + kk2 + tig + 4];
                af[mi][3] = As2[(mr + 8) * ASTRIDE + kk2 + tig + 4];
            }
            #pragma unroll
            for (int ni = 0; ni < 4; ni++) {
                const int nc = warpN * 32 + ni * 8 + gid;
                bf[ni][0] = Bs2[(kk2 + tig) * BSTRIDE + nc];
                bf[ni][1] = Bs2[(kk2 + tig + 4) * BSTRIDE + nc];
            }
            #pragma unroll
            for (int mi = 0; mi < 4; mi++)
                #pragma unroll
                for (int ni = 0; ni < 4; ni++)
                    MMA_F16(acc[mi][ni], af[mi][0], af[mi][1], af[mi][2],
                            af[mi][3], bf[ni][0], bf[ni][1]);
        }
        __syncthreads();
    }

    // Epilogue: bias (+ RoPE) (+ scale); half scatter or float row-major
    #pragma unroll
    for (int ni = 0; ni < 4; ni++) {
        const int c = n0 + warpN * 32 + ni * 8 + tig * 2;
        const float bv0 = bias[c], bv1 = bias[c + 1];
        #pragma unroll
        for (int mi = 0; mi < 4; mi++) {
            #pragma unroll
            for (int half_ = 0; half_ < 2; half_++) {
                const int r = m0 + warpM * 64 + mi * 16 + gid + half_ * 8;
                float v0 = acc[mi][ni][half_ * 2 + 0] + bv0;
                float v1 = acc[mi][ni][half_ * 2 + 1] + bv1;
                const int bb = r >> 11;
                const int s  = r & (S_ - 1);
                if (mode == 0 || mode == 3) {
                    const int pi = (c & (HD_ - 1)) >> 1;
                    const float cs = g_cos[s * (HD_ / 2) + pi];
                    const float sn = g_sin[s * (HD_ / 2) + pi];
                    const float e = v0, o = v1;
                    v0 = e * cs - o * sn;
                    v1 = o * cs + e * sn;
                    if (mode == 0) { v0 *= SCALE_; v1 *= SCALE_; }
                }
                if (mode != 2) {
                    const int h = (c >> 7) & (NH_ - 1);
                    const int d = c & (HD_ - 1);
                    __half* dst = (__half*)C +
                        (size_t)((bb * NH_ + h) * S_ + s) * HD_ + d;
                    *(unsigned*)dst = h2u(v0, v1);
                } else {
                    float2 val; val.x = v0; val.y = v1;
                    *(float2*)((float*)C + (size_t)r * GN + c) = val;
                }
            }
        }
    }
}

// ---------------------------------------------------------------------------
// Flash attention (causal), fp16 m16n8k16, half I/O.
// ---------------------------------------------------------------------------
#define QST 68
#define VST 136
#define QWORDS (64 * QST)

__global__ __launch_bounds__(128) void attn_h_kernel(
    const __half* __restrict__ q, const __half* __restrict__ k,
    const __half* __restrict__ v, __half* __restrict__ ctx)
{
    extern __shared__ unsigned smu[];
    unsigned* Qs2 = smu;
    unsigned* Ks2 = Qs2 + QWORDS;
    unsigned* Vs2 = Ks2 + QWORDS;

    const int tid  = threadIdx.x;
    const int lane = tid & 31, wid = tid >> 5;
    const int gid = lane >> 2, tig = lane & 3;
    const int bh = blockIdx.y;
    const int qt = gridDim.x - 1 - blockIdx.x;
    const int q0 = qt * 64;
    const int m0w = wid * 16;

    const __half* qp = q + ((size_t)bh * S_ + q0) * HD_;
    const __half* kb = k + (size_t)bh * S_ * HD_;
    const __half* vb = v + (size_t)bh * S_ * HD_;

    for (int t = tid; t < 64 * 16; t += 128) {
        int r = t >> 4, c = (t & 15) * 8;
        *(uint4*)&Qs2[r * QST + c / 2] = *(const uint4*)&qp[r * HD_ + c];
    }

    float oacc[16][4];
    #pragma unroll
    for (int ni = 0; ni < 16; ni++)
        #pragma unroll
        for (int u = 0; u < 4; u++) oacc[ni][u] = 0.f;
    float mx0 = -1e30f, mx1 = -1e30f, ls0 = 0.f, ls1 = 0.f;

    const int nkv = qt + 1;
    for (int kt = 0; kt < nkv; kt++) {
        const int k0 = kt * 64;
        __syncthreads();
        const __half* kp = kb + (size_t)k0 * HD_;
        const __half* vp = vb + (size_t)k0 * HD_;
        for (int t = tid; t < 64 * 16; t += 128) {
            int r = t >> 4, c = (t & 15) * 8;
            *(uint4*)&Ks2[r * QST + c / 2] = *(const uint4*)&kp[r * HD_ + c];
        }
        // V: s-interleave via byte_perm
        for (int t = tid; t < 32 * 32; t += 128) {
            int s2 = t >> 5, c = (t & 31) * 4;
            uint2 e = *(const uint2*)&vp[(2 * s2) * HD_ + c];
            uint2 o = *(const uint2*)&vp[(2 * s2 + 1) * HD_ + c];
            uint4 u;
            u.x = __byte_perm(e.x, o.x, 0x5410);
            u.y = __byte_perm(e.x, o.x, 0x7632);
            u.z = __byte_perm(e.y, o.y, 0x5410);
            u.w = __byte_perm(e.y, o.y, 0x7632);
            *(uint4*)&Vs2[s2 * VST + c] = u;
        }
        __syncthreads();

        float sacc[8][4];
        #pragma unroll
        for (int ni = 0; ni < 8; ni++)
            #pragma unroll
            for (int u = 0; u < 4; u++) sacc[ni][u] = 0.f;

        #pragma unroll
        for (int ks = 0; ks < 8; ks++) {
            const int kw = ks * 8;
            unsigned a0 = Qs2[(m0w + gid) * QST + kw + tig];
            unsigned a1 = Qs2[(m0w + gid + 8) * QST + kw + tig];
            unsigned a2 = Qs2[(m0w + gid) * QST + kw + tig + 4];
            unsigned a3 = Qs2[(m0w + gid + 8) * QST + kw + tig + 4];
            #pragma unroll
            for (int ni = 0; ni < 8; ni++) {
                unsigned b0 = Ks2[(ni * 8 + gid) * QST + kw + tig];
                unsigned b1 = Ks2[(ni * 8 + gid) * QST + kw + tig + 4];
                MMA_F16(sacc[ni], a0, a1, a2, a3, b0, b1);
            }
        }

        if (kt == nkv - 1) {
            const int row0 = q0 + m0w + gid;
            #pragma unroll
            for (int ni = 0; ni < 8; ni++) {
                const int col = k0 + ni * 8 + tig * 2;
                if (col > row0)     sacc[ni][0] = -1e30f;
                if (col + 1 > row0) sacc[ni][1] = -1e30f;
                if (col > row0 + 8)     sacc[ni][2] = -1e30f;
                if (col + 1 > row0 + 8) sacc[ni][3] = -1e30f;
            }
        }

        float rm0 = -1e30f, rm1 = -1e30f;
        #pragma unroll
        for (int ni = 0; ni < 8; ni++) {
            rm0 = fmaxf(rm0, fmaxf(sacc[ni][0], sacc[ni][1]));
            rm1 = fmaxf(rm1, fmaxf(sacc[ni][2], sacc[ni][3]));
        }
        rm0 = fmaxf(rm0, __shfl_xor_sync(0xffffffffu, rm0, 1));
        rm0 = fmaxf(rm0, __shfl_xor_sync(0xffffffffu, rm0, 2));
        rm1 = fmaxf(rm1, __shfl_xor_sync(0xffffffffu, rm1, 1));
        rm1 = fmaxf(rm1, __shfl_xor_sync(0xffffffffu, rm1, 2));

        const float mn0 = fmaxf(mx0, rm0), mn1 = fmaxf(mx1, rm1);
        const float f0 = __expf(mx0 - mn0), f1 = __expf(mx1 - mn1);
        float rs0 = 0.f, rs1 = 0.f;
        #pragma unroll
        for (int ni = 0; ni < 8; ni++) {
            float p0 = __expf(sacc[ni][0] - mn0);
            float p1 = __expf(sacc[ni][1] - mn0);
            float p2 = __expf(sacc[ni][2] - mn1);
            float p3 = __expf(sacc[ni][3] - mn1);
            sacc[ni][0] = p0; sacc[ni][1] = p1;
            sacc[ni][2] = p2; sacc[ni][3] = p3;
            rs0 += p0 + p1; rs1 += p2 + p3;
        }
        rs0 += __shfl_xor_sync(0xffffffffu, rs0, 1);
        rs0 += __shfl_xor_sync(0xffffffffu, rs0, 2);
        rs1 += __shfl_xor_sync(0xffffffffu, rs1, 1);
        rs1 += __shfl_xor_sync(0xffffffffu, rs1, 2);
        ls0 = ls0 * f0 + rs0; ls1 = ls1 * f1 + rs1;
        mx0 = mn0; mx1 = mn1;

        #pragma unroll
        for (int ni = 0; ni < 16; ni++) {
            oacc[ni][0] *= f0; oacc[ni][1] *= f0;
            oacc[ni][2] *= f1; oacc[ni][3] *= f1;
        }

        #pragma unroll
        for (int j = 0; j < 4; j++) {
            unsigned pa0 = h2u(sacc[2 * j][0], sacc[2 * j][1]);
            unsigned pa1 = h2u(sacc[2 * j][2], sacc[2 * j][3]);
            unsigned pa2 = h2u(sacc[2 * j + 1][0], sacc[2 * j + 1][1]);
            unsigned pa3 = h2u(sacc[2 * j + 1][2], sacc[2 * j + 1][3]);
            #pragma unroll
            for (int ni = 0; ni < 16; ni++) {
                const int nc = ni * 8 + gid;
                unsigned b0 = Vs2[(8 * j + tig) * VST + nc];
                unsigned b1 = Vs2[(8 * j + 4 + tig) * VST + nc];
                MMA_F16(oacc[ni], pa0, pa1, pa2, pa3, b0, b1);
            }
        }
    }

    const float inv0 = 1.f / ls0, inv1 = 1.f / ls1;
    const int b = bh >> 4, h = bh & 15;
    const int s0 = q0 + m0w + gid;
    #pragma unroll
    for (int ni = 0; ni < 16; ni++) {
        const int col = ni * 8 + tig * 2;
        *(unsigned*)&ctx[(size_t)(b * S_ + s0) * DM_ + h * HD_ + col] =
            h2u(oacc[ni][0] * inv0, oacc[ni][1] * inv0);
        *(unsigned*)&ctx[(size_t)(b * S_ + s0 + 8) * DM_ + h * HD_ + col] =
            h2u(oacc[ni][2] * inv1, oacc[ni][3] * inv1);
    }
}

// ---------------------------------------------------------------------------
// Launch
// ---------------------------------------------------------------------------
extern "C" void kernel_launch(void* const* d_in, const int* in_sizes, int n_in,
                              void* d_out, int out_size)
{
    const float* hs = (const float*)d_in[0];
    const float* Wq = (const float*)d_in[1];
    const float* bq = (const float*)d_in[2];
    const float* Wk = (const float*)d_in[3];
    const float* bk = (const float*)d_in[4];
    const float* Wv = (const float*)d_in[5];
    const float* bv = (const float*)d_in[6];
    const float* Wo = (const float*)d_in[7];
    const float* bo = (const float*)d_in[8];
    float* out = (float*)d_out;

    __half *qd, *kd, *vd, *ctxd, *ahd;
    unsigned* wtd;
    cudaGetSymbolAddress((void**)&qd,   g_qh);
    cudaGetSymbolAddress((void**)&kd,   g_kh);
    cudaGetSymbolAddress((void**)&vd,   g_vh);
    cudaGetSymbolAddress((void**)&ctxd, g_ctxh);
    cudaGetSymbolAddress((void**)&ahd,  g_ah);
    cudaGetSymbolAddress((void**)&wtd,  g_wt);
    unsigned* wq_t = wtd + 0 * (size_t)(DM_ / 2) * DM_;
    unsigned* wk_t = wtd + 1 * (size_t)(DM_ / 2) * DM_;
    unsigned* wv_t = wtd + 2 * (size_t)(DM_ / 2) * DM_;
    unsigned* wo_t = wtd + 3 * (size_t)(DM_ / 2) * DM_;

    const int gemm_smem = 3 * STAGEB;                       // 56832
    const int attn_smem = (2 * QWORDS + 32 * VST) * (int)sizeof(unsigned);
    static int smem_set = 0;
    if (!smem_set) {
        cudaFuncSetAttribute(hgemm2_kernel,
                             cudaFuncAttributeMaxDynamicSharedMemorySize,
                             gemm_smem);
        cudaFuncSetAttribute(attn_h_kernel,
                             cudaFuncAttributeMaxDynamicSharedMemorySize,
                             attn_smem);
        smem_set = 1;
    }

    rope_table_kernel<<<(S_ * (HD_ / 2) + 255) / 256, 256>>>();

    // Prepass: hs -> half, W -> k-pair-interleaved half2
    const int na8 = BS_ * DM_ / 8;
    const int nw  = (GK / 2) * (GN / 4);
    cvt_a_kernel<<<(na8 + 255) / 256, 256>>>(hs, ahd, na8);
    cvt_w_kernel<<<(nw + 255) / 256, 256>>>(Wq, wq_t);
    cvt_w_kernel<<<(nw + 255) / 256, 256>>>(Wk, wk_t);
    cvt_w_kernel<<<(nw + 255) / 256, 256>>>(Wv, wv_t);
    cvt_w_kernel<<<(nw + 255) / 256, 256>>>(Wo, wo_t);

    // Merged QKV: z=0 -> Q, z=1 -> K, z=2 -> V
    dim3 qkvgrid(GN / 128, 4096 / 128, 3);
    hgemm2_kernel<<<qkvgrid, 256, gemm_smem>>>(
        ahd, wq_t, wk_t, wv_t, bq, bk, bv, qd, kd, vd, -1);

    dim3 agrid(S_ / 64, B_ * NH_);
    attn_h_kernel<<<agrid, 128, attn_smem>>>(qd, kd, vd, ctxd);

    dim3 ogrid(GN / 128, 4096 / 128, 1);
    hgemm2_kernel<<<ogrid, 256, gemm_smem>>>(
        ctxd, wo_t, nullptr, nullptr, bo, nullptr, nullptr, out, nullptr,
        nullptr, 2);
}